// round 7
// baseline (speedup 1.0000x reference)
#include <cuda_runtime.h>
#include <math.h>

#define BB 16
#define NN 300000
#define NV 75000
#define NBLK 37
#define PRE 2000
#define POST 1000
#define CANDMAX 4096
#define MASKW 32
#define STAGE 1024

typedef unsigned long long ull;

__device__ unsigned g_phist[BB][NBLK][2048];
__device__ unsigned g_fhist[BB][NBLK][256];
__device__ unsigned g_done[BB];
__device__ int g_cut[BB];
__device__ unsigned g_ccount[BB];
__device__ ull g_cand[BB][CANDMAX];
__device__ float4 g_boxes[BB][PRE];
__device__ float g_area[BB][PRE];
__device__ int g_nvalid[BB];
__device__ ull g_mask[BB][PRE][MASKW];

__device__ __forceinline__ unsigned keyf(float f) {
    unsigned u = __float_as_uint(f);
    return u ^ ((u >> 31) ? 0xFFFFFFFFu : 0x80000000u);
}

__device__ __forceinline__ unsigned smaddr(const void* p) {
    return (unsigned)__cvta_generic_to_shared(p);
}
#define CP8(dst, src) asm volatile("cp.async.ca.shared.global [%0], [%1], 8;" :: "r"(dst), "l"(src))
#define CPCOMMIT() asm volatile("cp.async.commit_group;")
#define CPWAIT2() asm volatile("cp.async.wait_group 2;")
#define CPWAITALL() asm volatile("cp.async.wait_all;")

// Partial histograms (upper half of key space); the per-image LAST block
// (atomic ticket) reduces partials and computes the coarse cut in-kernel.
__global__ void __launch_bounds__(256) k_hist(const float* __restrict__ cls) {
    __shared__ unsigned sh[4096];
    __shared__ unsigned csum[256];
    __shared__ unsigned s_tick;
    __shared__ int sneed;
    int b = blockIdx.y;
    int t = threadIdx.x;
    for (int i = t; i < 2048; i += 256) sh[i] = 0u;
    __syncthreads();
    const float4* __restrict__ p = (const float4*)(cls + (size_t)b * NN);
    int base = blockIdx.x * 2048;
    if (base + 2048 <= NV) {
        float4 v[8];
#pragma unroll
        for (int k = 0; k < 8; k++) v[k] = p[base + t + 256 * k];
#pragma unroll
        for (int k = 0; k < 8; k++) {
            unsigned kk[4] = {keyf(v[k].x), keyf(v[k].y), keyf(v[k].z), keyf(v[k].w)};
#pragma unroll
            for (int q = 0; q < 4; q++)
                if (kk[q] >= 0x80000000u) atomicAdd(&sh[(kk[q] >> 20) - 2048], 1u);
        }
    } else {
        for (int k = 0; k < 8; k++) {
            int id = base + t + 256 * k;
            if (id < NV) {
                float4 v = p[id];
                unsigned kk[4] = {keyf(v.x), keyf(v.y), keyf(v.z), keyf(v.w)};
#pragma unroll
                for (int q = 0; q < 4; q++)
                    if (kk[q] >= 0x80000000u) atomicAdd(&sh[(kk[q] >> 20) - 2048], 1u);
            }
        }
    }
    __syncthreads();
    for (int i = t; i < 2048; i += 256) g_phist[b][blockIdx.x][i] = sh[i];
    __threadfence();
    __syncthreads();
    if (t == 0) s_tick = atomicAdd(&g_done[b], 1u);
    __syncthreads();
    if (s_tick != NBLK - 1) return;
    // ---- last block for image b: reduce + find cut ----
    __threadfence();
    unsigned loc[8] = {0, 0, 0, 0, 0, 0, 0, 0};
    for (int blk = 0; blk < NBLK; blk++) {
#pragma unroll
        for (int q = 0; q < 8; q++) loc[q] += g_phist[b][blk][t * 8 + q];
    }
    unsigned s = 0;
#pragma unroll
    for (int q = 0; q < 8; q++) { sh[t * 8 + q] = loc[q]; s += loc[q]; }
    csum[t] = s;
    __syncthreads();
    if (t == 0) {
        g_ccount[b] = 0u;
        g_done[b] = 0u;
        unsigned acc = 0;
        int found = 0;
        for (int c = 255; c >= 0; c--) {
            if (acc + csum[c] >= PRE) {
                for (int i = 7; i >= 0; i--) {
                    unsigned h = sh[c * 8 + i];
                    if (acc + h >= PRE) { g_cut[b] = 2048 + c * 8 + i; found = 1; break; }
                    acc += h;
                }
                break;
            }
            acc += csum[c];
        }
        sneed = !found;
        if (!found) g_cut[b] = 0;
    }
    __syncthreads();
    if (sneed) {  // cold fallback: full-range histogram by this block
        for (int i = t; i < 4096; i += 256) sh[i] = 0u;
        __syncthreads();
        for (int id = t; id < NV; id += 256) {
            float4 v = p[id];
            atomicAdd(&sh[keyf(v.x) >> 20], 1u);
            atomicAdd(&sh[keyf(v.y) >> 20], 1u);
            atomicAdd(&sh[keyf(v.z) >> 20], 1u);
            atomicAdd(&sh[keyf(v.w) >> 20], 1u);
        }
        __syncthreads();
        unsigned s2 = 0;
        for (int q = 0; q < 16; q++) s2 += sh[t * 16 + q];
        csum[t] = s2;
        __syncthreads();
        if (t == 0) {
            unsigned acc = 0;
            for (int c = 255; c >= 0; c--) {
                if (acc + csum[c] >= PRE) {
                    for (int i = 15; i >= 0; i--) {
                        unsigned h = sh[c * 16 + i];
                        if (acc + h >= PRE) { g_cut[b] = c * 16 + i; return; }
                        acc += h;
                    }
                    return;
                }
                acc += csum[c];
            }
            g_cut[b] = 0;
        }
    }
}

// Compact + fine (8-bit) histogram of the cut bin (bits 12..19 of the key).
__global__ void __launch_bounds__(256) k_compact(const float* __restrict__ cls) {
    __shared__ ull stage[STAGE];
    __shared__ unsigned fsh[256];
    __shared__ unsigned s_cnt, s_base;
    int b = blockIdx.y;
    int t = threadIdx.x;
    int cut = g_cut[b];
    if (t == 0) s_cnt = 0u;
    fsh[t] = 0u;
    __syncthreads();
    const float4* __restrict__ p = (const float4*)(cls + (size_t)b * NN);
    int base = blockIdx.x * 2048;
    if (base + 2048 <= NV) {
        float4 v[8];
#pragma unroll
        for (int k = 0; k < 8; k++) v[k] = p[base + t + 256 * k];
#pragma unroll
        for (int k = 0; k < 8; k++) {
            int id = base + t + 256 * k;
            unsigned kk[4] = {keyf(v[k].x), keyf(v[k].y), keyf(v[k].z), keyf(v[k].w)};
#pragma unroll
            for (int q = 0; q < 4; q++) {
                if ((int)(kk[q] >> 20) >= cut) {
                    unsigned r = atomicAdd(&s_cnt, 1u);
                    if (r < STAGE)
                        stage[r] = ((ull)kk[q] << 32) | (unsigned)(~(4 * id + q));
                    if ((int)(kk[q] >> 20) == cut) atomicAdd(&fsh[(kk[q] >> 12) & 0xFF], 1u);
                }
            }
        }
    } else {
        for (int k = 0; k < 8; k++) {
            int id = base + t + 256 * k;
            if (id < NV) {
                float4 v = p[id];
                unsigned kk[4] = {keyf(v.x), keyf(v.y), keyf(v.z), keyf(v.w)};
#pragma unroll
                for (int q = 0; q < 4; q++) {
                    if ((int)(kk[q] >> 20) >= cut) {
                        unsigned r = atomicAdd(&s_cnt, 1u);
                        if (r < STAGE)
                            stage[r] = ((ull)kk[q] << 32) | (unsigned)(~(4 * id + q));
                        if ((int)(kk[q] >> 20) == cut) atomicAdd(&fsh[(kk[q] >> 12) & 0xFF], 1u);
                    }
                }
            }
        }
    }
    __syncthreads();
    g_fhist[b][blockIdx.x][t] = fsh[t];
    if (t == 0) {
        unsigned c = s_cnt < STAGE ? s_cnt : STAGE;
        s_base = atomicAdd(&g_ccount[b], c);
    }
    __syncthreads();
    unsigned c = s_cnt < STAGE ? s_cnt : STAGE;
    for (unsigned r = t; r < c; r += 256) {
        unsigned pos = s_base + r;
        if (pos < CANDMAX) g_cand[b][pos] = stage[r];
    }
}

#define CSW(a, c, d) { if ((d) ? ((a) < (c)) : ((a) > (c))) { ull _t = (a); (a) = (c); (c) = _t; } }
#define KM(e, o) ((kmax) ? ((e) > (o) ? (e) : (o)) : ((e) < (o) ? (e) : (o)))
#define SHFLP() { \
    int m = j >> 2; \
    bool kmax = (desc != ((tid & m) != 0)); \
    ull o0 = __shfl_xor_sync(0xffffffffu, e0, m); \
    ull o1 = __shfl_xor_sync(0xffffffffu, e1, m); \
    ull o2 = __shfl_xor_sync(0xffffffffu, e2, m); \
    ull o3 = __shfl_xor_sync(0xffffffffu, e3, m); \
    e0 = KM(e0, o0); e1 = KM(e1, o1); e2 = KM(e2, o2); e3 = KM(e3, o3); }

__global__ void __launch_bounds__(1024)
k_sortdecode(const float* __restrict__ reg, const float* __restrict__ anchors) {
    __shared__ ull sk[CANDMAX];
    __shared__ int swsum[32];
    __shared__ unsigned fh[256];
    __shared__ int s_fcut, s_kept;
    int b = blockIdx.x;
    int tid = threadIdx.x;
    unsigned n = g_ccount[b];
    if (n > CANDMAX) n = CANDMAX;
    int lane = tid & 31, wid = tid >> 5;
    // ---- fine cut from fine histogram ----
    if (tid < 256) {
        unsigned s = 0;
        for (int blk = 0; blk < NBLK; blk++) s += g_fhist[b][blk][tid];
        fh[tid] = s;
    }
    __syncthreads();
    if (tid == 0) {
        unsigned tie = 0;
        for (int f = 0; f < 256; f++) tie += fh[f];
        int nab = (int)n - (int)tie;
        int acc = 0, fcut = 0, kept = (int)n;
        for (int f = 255; f >= 0; f--) {
            if (nab + acc + (int)fh[f] >= PRE) { fcut = f; kept = nab + acc + (int)fh[f]; break; }
            acc += (int)fh[f];
        }
        s_fcut = fcut;
        s_kept = kept;
    }
    __syncthreads();
    int kept = s_kept, fcut = s_fcut, cut = g_cut[b];
    int b4 = 4 * tid;
    ull e0 = 0, e1 = 0, e2 = 0, e3 = 0;
    if (kept <= 2048) {
        // ---- filter to kept superset, compact into sk[0..2048), sort 2048 ----
        ull c0 = 0, c1 = 0, c2 = 0, c3 = 0;
        int p0 = 0, p1 = 0, p2 = 0, p3 = 0;
#define LOADP(ci, pi, off) { int e = b4 + off; \
        if (e < (int)n) { ci = g_cand[b][e]; unsigned key = (unsigned)(ci >> 32); \
            pi = ((int)(key >> 20) > cut) || ((int)((key >> 12) & 0xFF) >= fcut); } }
        LOADP(c0, p0, 0) LOADP(c1, p1, 1) LOADP(c2, p2, 2) LOADP(c3, p3, 3)
#undef LOADP
        int cnt = p0 + p1 + p2 + p3;
        int v = cnt;
        for (int o = 1; o < 32; o <<= 1) {
            int t2 = __shfl_up_sync(0xffffffffu, v, o);
            if (lane >= o) v += t2;
        }
        if (lane == 31) swsum[wid] = v;
        __syncthreads();
        if (wid == 0) {
            int x = swsum[lane];
            for (int o = 1; o < 32; o <<= 1) {
                int t2 = __shfl_up_sync(0xffffffffu, x, o);
                if (lane >= o) x += t2;
            }
            swsum[lane] = x;
        }
        __syncthreads();
        int excl = v - cnt + (wid ? swsum[wid - 1] : 0);
        sk[tid] = 0ULL;
        sk[tid + 1024] = 0ULL;
        __syncthreads();
        int pos = excl;
        if (p0) sk[pos++] = c0;
        if (p1) sk[pos++] = c1;
        if (p2) sk[pos++] = c2;
        if (p3) sk[pos++] = c3;
        __syncthreads();
        bool act = (tid < 512);
        if (act) {
            e0 = sk[b4]; e1 = sk[b4 + 1]; e2 = sk[b4 + 2]; e3 = sk[b4 + 3];
            CSW(e0, e1, true);
            CSW(e2, e3, false);
        }
        for (int k = 4; k <= 2048; k <<= 1) {
            bool desc = ((b4 & k) == 0);
            for (int j = k >> 1; j >= 128; j >>= 1) {
                if (act) { sk[b4] = e0; sk[b4 + 1] = e1; sk[b4 + 2] = e2; sk[b4 + 3] = e3; }
                __syncthreads();
                if (act) {
                    int m = j >> 2;
                    int pt = 4 * (tid ^ m);
                    bool kmax = (desc != ((tid & m) != 0));
                    ull o0 = sk[pt], o1 = sk[pt + 1], o2 = sk[pt + 2], o3 = sk[pt + 3];
                    e0 = KM(e0, o0); e1 = KM(e1, o1); e2 = KM(e2, o2); e3 = KM(e3, o3);
                }
                __syncthreads();
            }
            if (act) {
                int jstart = (k >> 1) < 64 ? (k >> 1) : 64;
                for (int j = jstart; j >= 4; j >>= 1) SHFLP()
                CSW(e0, e2, desc); CSW(e1, e3, desc);
                CSW(e0, e1, desc); CSW(e2, e3, desc);
            }
        }
        if (act) { sk[b4] = e0; sk[b4 + 1] = e1; sk[b4 + 2] = e2; sk[b4 + 3] = e3; }
        __syncthreads();
    } else {
        // ---- fallback: full 4096 sort ----
        e0 = (b4 + 0 < (int)n) ? g_cand[b][b4 + 0] : 0ULL;
        e1 = (b4 + 1 < (int)n) ? g_cand[b][b4 + 1] : 0ULL;
        e2 = (b4 + 2 < (int)n) ? g_cand[b][b4 + 2] : 0ULL;
        e3 = (b4 + 3 < (int)n) ? g_cand[b][b4 + 3] : 0ULL;
        CSW(e0, e1, true);
        CSW(e2, e3, false);
        for (int k = 4; k <= CANDMAX; k <<= 1) {
            bool desc = ((b4 & k) == 0);
            for (int j = k >> 1; j >= 128; j >>= 1) {
                sk[b4] = e0; sk[b4 + 1] = e1; sk[b4 + 2] = e2; sk[b4 + 3] = e3;
                __syncthreads();
                int m = j >> 2;
                int pt = 4 * (tid ^ m);
                bool kmax = (desc != ((tid & m) != 0));
                ull o0 = sk[pt], o1 = sk[pt + 1], o2 = sk[pt + 2], o3 = sk[pt + 3];
                e0 = KM(e0, o0); e1 = KM(e1, o1); e2 = KM(e2, o2); e3 = KM(e3, o3);
                __syncthreads();
            }
            int jstart = (k >> 1) < 64 ? (k >> 1) : 64;
            for (int j = jstart; j >= 4; j >>= 1) SHFLP()
            CSW(e0, e2, desc); CSW(e1, e3, desc);
            CSW(e0, e1, desc); CSW(e2, e3, desc);
        }
        sk[b4] = e0; sk[b4 + 1] = e1; sk[b4 + 2] = e2; sk[b4 + 3] = e3;
        __syncthreads();
    }
    // ---- decode + stable valid-first partition ----
    float4 box[2];
    int val[2];
#pragma unroll
    for (int q = 0; q < 2; q++) {
        int e = 2 * tid + q;
        val[q] = 0;
        box[q] = make_float4(0.f, 0.f, 0.f, 0.f);
        if (e < PRE) {
            unsigned idx = ~(unsigned)(sk[e] & 0xFFFFFFFFULL);
            const float* a = anchors + ((size_t)b * NN + idx) * 4;
            const float* r = reg + ((size_t)b * NN + idx) * 4;
            float a0 = a[0], a1 = a[1], a2 = a[2], a3 = a[3];
            float dx = r[0], dy = r[1], dw = r[2], dh = r[3];
            float aw = a2 - a0, ah = a3 - a1;
            float acx = a0 + 0.5f * aw, acy = a1 + 0.5f * ah;
            float pcx = dx * aw + acx, pcy = dy * ah + acy;
            float pw = expf(dw) * aw, ph = expf(dh) * ah;
            float x1 = pcx - 0.5f * pw, y1 = pcy - 0.5f * ph;
            float x2 = pcx + 0.5f * pw, y2 = pcy + 0.5f * ph;
            x1 = fminf(fmaxf(x1, 0.f), 1333.f);
            y1 = fminf(fmaxf(y1, 0.f), 800.f);
            x2 = fminf(fmaxf(x2, 0.f), 1333.f);
            y2 = fminf(fmaxf(y2, 0.f), 800.f);
            float w = x2 - x1, h = y2 - y1;
            val[q] = (w >= 0.001f && h >= 0.001f) ? 1 : 0;
            box[q] = make_float4(x1, y1, x2, y2);
        }
    }
    int pairsum = val[0] + val[1];
    int v = pairsum;
    for (int o = 1; o < 32; o <<= 1) {
        int t2 = __shfl_up_sync(0xffffffffu, v, o);
        if (lane >= o) v += t2;
    }
    if (lane == 31) swsum[wid] = v;
    __syncthreads();
    if (wid == 0) {
        int x = swsum[lane];
        for (int o = 1; o < 32; o <<= 1) {
            int t2 = __shfl_up_sync(0xffffffffu, x, o);
            if (lane >= o) x += t2;
        }
        swsum[lane] = x;
    }
    __syncthreads();
    int incl = v + (wid ? swsum[wid - 1] : 0);
    int excl = incl - pairsum;
    int nv = swsum[31];
    int ea = 2 * tid, eb = 2 * tid + 1;
    int rank0 = excl;
    int rank1 = excl + val[0];
    int pos0 = val[0] ? rank0 : nv + (ea - rank0);
    int pos1 = val[1] ? rank1 : nv + (eb - rank1);
    if (ea < PRE) {
        g_boxes[b][pos0] = box[0];
        g_area[b][pos0] = (box[0].z - box[0].x) * (box[0].w - box[0].y);
    }
    if (eb < PRE) {
        g_boxes[b][pos1] = box[1];
        g_area[b][pos1] = (box[1].z - box[1].x) * (box[1].w - box[1].y);
    }
    if (tid == 0) g_nvalid[b] = nv;
}

__global__ void __launch_bounds__(64) k_mask() {
    int b = blockIdx.y;
    int t = threadIdx.x;
    int lin = blockIdx.x, rblk = 0;
    while (lin >= 32 - rblk) { lin -= 32 - rblk; rblk++; }
    int cblk = rblk + lin;
    int rb = rblk << 6, cb = cblk << 6;
    __shared__ float4 cbox[64];
    __shared__ float carea[64];
    {
        int j0 = cb + t;
        cbox[t] = (j0 < PRE) ? g_boxes[b][j0] : make_float4(-1.f, -1.f, -1.f, -1.f);
        carea[t] = (j0 < PRE) ? g_area[b][j0] : 0.f;
    }
    __syncthreads();
    int i = rb + t;
    if (i >= PRE) return;
    float4 bi = g_boxes[b][i];
    float areai = g_area[b][i];
    ull bits = 0ULL, amb = 0ULL;
    int c0 = (cblk == rblk) ? (t + 1) : 0;
#pragma unroll 8
    for (int c = c0; c < 64; c++) {
        float4 bj = cbox[c];
        float w = fmaxf(fminf(bi.z, bj.z) - fmaxf(bi.x, bj.x), 0.f);
        float h = fmaxf(fminf(bi.w, bj.w) - fmaxf(bi.y, bj.y), 0.f);
        float inter = w * h;
        float um = fmaxf((areai + carea[c]) - inter, 1e-8f);
        bool s1 = inter > 0.70000210f * um;
        bool a1 = (!s1) && (inter >= 0.69999790f * um);
        bits |= ((ull)s1) << c;
        amb |= ((ull)a1) << c;
    }
    while (amb) {
        int c = __ffsll(amb) - 1;
        amb &= amb - 1;
        float4 bj = cbox[c];
        float w = fmaxf(fminf(bi.z, bj.z) - fmaxf(bi.x, bj.x), 0.f);
        float h = fmaxf(fminf(bi.w, bj.w) - fmaxf(bi.y, bj.y), 0.f);
        float inter = w * h;
        float um = fmaxf((areai + carea[c]) - inter, 1e-8f);
        if (__fdiv_rn(inter, um) > 0.7f) bits |= 1ULL << c;
    }
    g_mask[b][i][cblk] = bits;
}

__global__ void __launch_bounds__(256) k_scan(float4* __restrict__ out) {
    __shared__ ull ring[4][16][32];
    __shared__ int sel[POST];
    __shared__ int skc;
    int b = blockIdx.x;
    int tid = threadIdx.x;
    if (tid < 32) {
        int lane = tid;
        int nv = g_nvalid[b];
        int lo = lane * 64;
        ull rem;
        if (nv <= lo) rem = ~0ULL;
        else if (nv >= lo + 64) rem = 0ULL;
        else rem = (~0ULL) << (nv - lo);
        for (int nb = 0; nb < 3; nb++) {
#pragma unroll
            for (int q = 0; q < 16; q++)
                CP8(smaddr(&ring[nb][q][lane]), &g_mask[b][nb * 16 + q][lane]);
            CPCOMMIT();
        }
        int limit = (PRE < nv) ? PRE : nv;
        int kc = 0, w = 0;
        ull r = 0ULL;
        for (int bt = 0; bt < PRE / 16; bt++) {
            CPWAIT2();
            __syncwarp();
            int base = bt * 16;
            if (base >= limit) break;
            if ((base & 63) == 0) {
                w = base >> 6;
                r = __shfl_sync(0xffffffffu, rem, w);
            }
            ull m[16];
            unsigned keptm = 0;
            if (lane == 0) {
#pragma unroll
                for (int q = 0; q < 16; q++) m[q] = ring[bt & 3][q][w];
                int off = base & 63;
#pragma unroll
                for (int q = 0; q < 16; q++) {
                    int row = base + q;
                    bool keep = (row < limit) && !((r >> (off + q)) & 1ULL);
                    if (keep) {
                        if (kc < POST) sel[kc] = row;
                        kc++;
                        keptm |= 1u << q;
                        r |= m[q];
                    }
                }
            }
            keptm = __shfl_sync(0xffffffffu, keptm, 0);
            ull acc = 0ULL;
#pragma unroll
            for (int q = 0; q < 16; q++)
                if ((keptm >> q) & 1u) acc |= ring[bt & 3][q][lane];
            if (lane >= w) rem |= acc;
            kc = __shfl_sync(0xffffffffu, kc, 0);
            if (kc >= POST) break;
            int nb = bt + 3;
            if (nb < PRE / 16) {
#pragma unroll
                for (int q = 0; q < 16; q++)
                    CP8(smaddr(&ring[nb & 3][q][lane]), &g_mask[b][nb * 16 + q][lane]);
            }
            CPCOMMIT();
        }
        CPWAITALL();
        if (lane == 0) skc = (kc < POST) ? kc : POST;
    }
    __syncthreads();
    int kc = skc;
    for (int k = tid; k < POST; k += blockDim.x) {
        float4 v = make_float4(0.f, 0.f, 0.f, 0.f);
        if (k < kc) v = g_boxes[b][sel[k]];
        out[(size_t)b * POST + k] = v;
    }
}

extern "C" void kernel_launch(void* const* d_in, const int* in_sizes, int n_in,
                              void* d_out, int out_size) {
    const float* cls = (const float*)d_in[0];
    const float* reg = (const float*)d_in[1];
    const float* anchors = (const float*)d_in[2];
    float4* out = (float4*)d_out;

    k_hist<<<dim3(NBLK, BB), 256>>>(cls);
    k_compact<<<dim3(NBLK, BB), 256>>>(cls);
    k_sortdecode<<<BB, 1024>>>(reg, anchors);
    k_mask<<<dim3(528, BB), 64>>>();
    k_scan<<<BB, 256>>>(out);
}

// round 8
// speedup vs baseline: 1.0518x; 1.0518x over previous
#include <cuda_runtime.h>
#include <math.h>

#define BB 16
#define NN 300000
#define NV 75000
#define NBLK 37
#define PRE 2000
#define POST 1000
#define CANDMAX 4096
#define MASKW 32
#define STAGE 1024

typedef unsigned long long ull;

__device__ unsigned g_phist[BB][NBLK][2048];
__device__ int g_cut[BB];
__device__ unsigned g_ccount[BB];
__device__ ull g_cand[BB][CANDMAX];
__device__ float4 g_boxes[BB][PRE];
__device__ float g_area[BB][PRE];
__device__ int g_nvalid[BB];
__device__ ull g_mask[BB][PRE][MASKW];

__device__ __forceinline__ unsigned keyf(float f) {
    unsigned u = __float_as_uint(f);
    return u ^ ((u >> 31) ? 0xFFFFFFFFu : 0x80000000u);
}

__device__ __forceinline__ unsigned smaddr(const void* p) {
    return (unsigned)__cvta_generic_to_shared(p);
}
#define CP8(dst, src) asm volatile("cp.async.ca.shared.global [%0], [%1], 8;" :: "r"(dst), "l"(src))
#define CPCOMMIT() asm volatile("cp.async.commit_group;")
#define CPWAIT2() asm volatile("cp.async.wait_group 2;")
#define CPWAITALL() asm volatile("cp.async.wait_all;")

__global__ void __launch_bounds__(256) k_hist(const float* __restrict__ cls) {
    __shared__ unsigned sh[2048];
    int b = blockIdx.y;
    int t = threadIdx.x;
    for (int i = t; i < 2048; i += 256) sh[i] = 0u;
    __syncthreads();
    const float4* __restrict__ p = (const float4*)(cls + (size_t)b * NN);
    int base = blockIdx.x * 2048;
    if (base + 2048 <= NV) {
        float4 v[8];
#pragma unroll
        for (int k = 0; k < 8; k++) v[k] = p[base + t + 256 * k];
#pragma unroll
        for (int k = 0; k < 8; k++) {
            unsigned kk[4] = {keyf(v[k].x), keyf(v[k].y), keyf(v[k].z), keyf(v[k].w)};
#pragma unroll
            for (int q = 0; q < 4; q++)
                if (kk[q] >= 0x80000000u) atomicAdd(&sh[(kk[q] >> 20) - 2048], 1u);
        }
    } else {
        for (int k = 0; k < 8; k++) {
            int id = base + t + 256 * k;
            if (id < NV) {
                float4 v = p[id];
                unsigned kk[4] = {keyf(v.x), keyf(v.y), keyf(v.z), keyf(v.w)};
#pragma unroll
                for (int q = 0; q < 4; q++)
                    if (kk[q] >= 0x80000000u) atomicAdd(&sh[(kk[q] >> 20) - 2048], 1u);
            }
        }
    }
    __syncthreads();
    for (int i = t; i < 2048; i += 256) g_phist[b][blockIdx.x][i] = sh[i];
}

__global__ void __launch_bounds__(256) k_cut(const float* __restrict__ cls) {
    __shared__ unsigned hist[2048];
    __shared__ unsigned csum[256];
    __shared__ int sneed;
    int b = blockIdx.x;
    int t = threadIdx.x;
    unsigned loc[8] = {0, 0, 0, 0, 0, 0, 0, 0};
    for (int blk = 0; blk < NBLK; blk++) {
#pragma unroll
        for (int q = 0; q < 8; q++) loc[q] += g_phist[b][blk][t * 8 + q];
    }
    unsigned s = 0;
#pragma unroll
    for (int q = 0; q < 8; q++) { hist[t * 8 + q] = loc[q]; s += loc[q]; }
    csum[t] = s;
    __syncthreads();
    if (t == 0) {
        g_ccount[b] = 0u;
        unsigned acc = 0;
        int found = 0;
        for (int c = 255; c >= 0; c--) {
            if (acc + csum[c] >= PRE) {
                for (int i = 7; i >= 0; i--) {
                    unsigned h = hist[c * 8 + i];
                    if (acc + h >= PRE) { g_cut[b] = 2048 + c * 8 + i; found = 1; break; }
                    acc += h;
                }
                break;
            }
            acc += csum[c];
        }
        sneed = !found;
        if (!found) g_cut[b] = 0;
    }
    __syncthreads();
    if (sneed) {  // cold fallback: full-range histogram by this one block
        __shared__ unsigned fh[4096];
        for (int i = t; i < 4096; i += 256) fh[i] = 0u;
        __syncthreads();
        const float4* __restrict__ p = (const float4*)(cls + (size_t)b * NN);
        for (int id = t; id < NV; id += 256) {
            float4 v = p[id];
            atomicAdd(&fh[keyf(v.x) >> 20], 1u);
            atomicAdd(&fh[keyf(v.y) >> 20], 1u);
            atomicAdd(&fh[keyf(v.z) >> 20], 1u);
            atomicAdd(&fh[keyf(v.w) >> 20], 1u);
        }
        __syncthreads();
        unsigned s2 = 0;
        for (int q = 0; q < 16; q++) s2 += fh[t * 16 + q];
        csum[t] = s2;
        __syncthreads();
        if (t == 0) {
            unsigned acc = 0;
            for (int c = 255; c >= 0; c--) {
                if (acc + csum[c] >= PRE) {
                    for (int i = 15; i >= 0; i--) {
                        unsigned h = fh[c * 16 + i];
                        if (acc + h >= PRE) { g_cut[b] = c * 16 + i; return; }
                        acc += h;
                    }
                    return;
                }
                acc += csum[c];
            }
            g_cut[b] = 0;
        }
    }
}

__global__ void __launch_bounds__(256) k_compact(const float* __restrict__ cls) {
    __shared__ ull stage[STAGE];
    __shared__ unsigned s_cnt, s_base;
    int b = blockIdx.y;
    int t = threadIdx.x;
    int cut = g_cut[b];
    if (t == 0) s_cnt = 0u;
    __syncthreads();
    const float4* __restrict__ p = (const float4*)(cls + (size_t)b * NN);
    int base = blockIdx.x * 2048;
    if (base + 2048 <= NV) {
        float4 v[8];
#pragma unroll
        for (int k = 0; k < 8; k++) v[k] = p[base + t + 256 * k];
#pragma unroll
        for (int k = 0; k < 8; k++) {
            int id = base + t + 256 * k;
            unsigned kk[4] = {keyf(v[k].x), keyf(v[k].y), keyf(v[k].z), keyf(v[k].w)};
#pragma unroll
            for (int q = 0; q < 4; q++) {
                if ((int)(kk[q] >> 20) >= cut) {
                    unsigned r = atomicAdd(&s_cnt, 1u);
                    if (r < STAGE)
                        stage[r] = ((ull)kk[q] << 32) | (unsigned)(~(4 * id + q));
                }
            }
        }
    } else {
        for (int k = 0; k < 8; k++) {
            int id = base + t + 256 * k;
            if (id < NV) {
                float4 v = p[id];
                unsigned kk[4] = {keyf(v.x), keyf(v.y), keyf(v.z), keyf(v.w)};
#pragma unroll
                for (int q = 0; q < 4; q++) {
                    if ((int)(kk[q] >> 20) >= cut) {
                        unsigned r = atomicAdd(&s_cnt, 1u);
                        if (r < STAGE)
                            stage[r] = ((ull)kk[q] << 32) | (unsigned)(~(4 * id + q));
                    }
                }
            }
        }
    }
    __syncthreads();
    if (t == 0) {
        unsigned c = s_cnt < STAGE ? s_cnt : STAGE;
        s_base = atomicAdd(&g_ccount[b], c);
    }
    __syncthreads();
    unsigned c = s_cnt < STAGE ? s_cnt : STAGE;
    for (unsigned r = t; r < c; r += 256) {
        unsigned pos = s_base + r;
        if (pos < CANDMAX) g_cand[b][pos] = stage[r];
    }
}

#define CSW(a, c, d) { if ((d) ? ((a) < (c)) : ((a) > (c))) { ull _t = (a); (a) = (c); (c) = _t; } }
#define KM(e, o) ((kmax) ? ((e) > (o) ? (e) : (o)) : ((e) < (o) ? (e) : (o)))

__global__ void __launch_bounds__(1024)
k_sortdecode(const float* __restrict__ reg, const float* __restrict__ anchors) {
    __shared__ ull sk[CANDMAX];
    __shared__ int swsum[32];
    int b = blockIdx.x;
    int tid = threadIdx.x;
    unsigned n = g_ccount[b];
    if (n > CANDMAX) n = CANDMAX;
    int base4 = 4 * tid;
    ull e0 = (base4 + 0 < (int)n) ? g_cand[b][base4 + 0] : 0ULL;
    ull e1 = (base4 + 1 < (int)n) ? g_cand[b][base4 + 1] : 0ULL;
    ull e2 = (base4 + 2 < (int)n) ? g_cand[b][base4 + 2] : 0ULL;
    ull e3 = (base4 + 3 < (int)n) ? g_cand[b][base4 + 3] : 0ULL;
    CSW(e0, e1, true);
    CSW(e2, e3, false);
    for (int k = 4; k <= CANDMAX; k <<= 1) {
        bool desc = ((base4 & k) == 0);
        for (int j = k >> 1; j >= 128; j >>= 1) {
            sk[base4] = e0; sk[base4 + 1] = e1; sk[base4 + 2] = e2; sk[base4 + 3] = e3;
            __syncthreads();
            int m = j >> 2;
            int pt = 4 * (tid ^ m);
            bool kmax = (desc != ((tid & m) != 0));
            ull o0 = sk[pt], o1 = sk[pt + 1], o2 = sk[pt + 2], o3 = sk[pt + 3];
            e0 = KM(e0, o0); e1 = KM(e1, o1); e2 = KM(e2, o2); e3 = KM(e3, o3);
            __syncthreads();
        }
        int jstart = (k >> 1) < 64 ? (k >> 1) : 64;
        for (int j = jstart; j >= 4; j >>= 1) {
            int m = j >> 2;
            bool kmax = (desc != ((tid & m) != 0));
            ull o0 = __shfl_xor_sync(0xffffffffu, e0, m);
            ull o1 = __shfl_xor_sync(0xffffffffu, e1, m);
            ull o2 = __shfl_xor_sync(0xffffffffu, e2, m);
            ull o3 = __shfl_xor_sync(0xffffffffu, e3, m);
            e0 = KM(e0, o0); e1 = KM(e1, o1); e2 = KM(e2, o2); e3 = KM(e3, o3);
        }
        CSW(e0, e2, desc); CSW(e1, e3, desc);
        CSW(e0, e1, desc); CSW(e2, e3, desc);
    }
    sk[base4] = e0; sk[base4 + 1] = e1; sk[base4 + 2] = e2; sk[base4 + 3] = e3;
    __syncthreads();

    float4 box[2];
    int val[2];
#pragma unroll
    for (int q = 0; q < 2; q++) {
        int e = 2 * tid + q;
        val[q] = 0;
        box[q] = make_float4(0.f, 0.f, 0.f, 0.f);
        if (e < PRE) {
            unsigned idx = ~(unsigned)(sk[e] & 0xFFFFFFFFULL);
            const float* a = anchors + ((size_t)b * NN + idx) * 4;
            const float* r = reg + ((size_t)b * NN + idx) * 4;
            float a0 = a[0], a1 = a[1], a2 = a[2], a3 = a[3];
            float dx = r[0], dy = r[1], dw = r[2], dh = r[3];
            float aw = a2 - a0, ah = a3 - a1;
            float acx = a0 + 0.5f * aw, acy = a1 + 0.5f * ah;
            float pcx = dx * aw + acx, pcy = dy * ah + acy;
            float pw = expf(dw) * aw, ph = expf(dh) * ah;
            float x1 = pcx - 0.5f * pw, y1 = pcy - 0.5f * ph;
            float x2 = pcx + 0.5f * pw, y2 = pcy + 0.5f * ph;
            x1 = fminf(fmaxf(x1, 0.f), 1333.f);
            y1 = fminf(fmaxf(y1, 0.f), 800.f);
            x2 = fminf(fmaxf(x2, 0.f), 1333.f);
            y2 = fminf(fmaxf(y2, 0.f), 800.f);
            float w = x2 - x1, h = y2 - y1;
            val[q] = (w >= 0.001f && h >= 0.001f) ? 1 : 0;
            box[q] = make_float4(x1, y1, x2, y2);
        }
    }
    int pairsum = val[0] + val[1];
    int lane = tid & 31, wid = tid >> 5;
    int v = pairsum;
    for (int o = 1; o < 32; o <<= 1) {
        int t2 = __shfl_up_sync(0xffffffffu, v, o);
        if (lane >= o) v += t2;
    }
    if (lane == 31) swsum[wid] = v;
    __syncthreads();
    if (wid == 0) {
        int x = swsum[lane];
        for (int o = 1; o < 32; o <<= 1) {
            int t2 = __shfl_up_sync(0xffffffffu, x, o);
            if (lane >= o) x += t2;
        }
        swsum[lane] = x;
    }
    __syncthreads();
    int incl = v + (wid ? swsum[wid - 1] : 0);
    int excl = incl - pairsum;
    int nv = swsum[31];
    int ea = 2 * tid, eb = 2 * tid + 1;
    int rank0 = excl;
    int rank1 = excl + val[0];
    int pos0 = val[0] ? rank0 : nv + (ea - rank0);
    int pos1 = val[1] ? rank1 : nv + (eb - rank1);
    if (ea < PRE) {
        g_boxes[b][pos0] = box[0];
        g_area[b][pos0] = (box[0].z - box[0].x) * (box[0].w - box[0].y);
    }
    if (eb < PRE) {
        g_boxes[b][pos1] = box[1];
        g_area[b][pos1] = (box[1].z - box[1].x) * (box[1].w - box[1].y);
    }
    if (tid == 0) g_nvalid[b] = nv;
}

// IoU body for one row against staged columns [c0, 64), accumulating
// suppress + ambiguity bits. Exactness preserved via rare fdiv fallback.
__device__ __forceinline__ void iou_row(const float4& bi, float areai,
                                        const float4* cbox, const float* carea,
                                        int c0, ull& bits) {
    ull amb = 0ULL;
#pragma unroll 16
    for (int c = c0; c < 64; c++) {
        float4 bj = cbox[c];
        float w = fmaxf(fminf(bi.z, bj.z) - fmaxf(bi.x, bj.x), 0.f);
        float h = fmaxf(fminf(bi.w, bj.w) - fmaxf(bi.y, bj.y), 0.f);
        float inter = w * h;
        float um = fmaxf((areai + carea[c]) - inter, 1e-8f);
        bool s1 = inter > 0.70000210f * um;
        bool a1 = (!s1) && (inter >= 0.69999790f * um);
        bits |= ((ull)s1) << c;
        amb |= ((ull)a1) << c;
    }
    while (amb) {
        int c = __ffsll(amb) - 1;
        amb &= amb - 1;
        float4 bj = cbox[c];
        float w = fmaxf(fminf(bi.z, bj.z) - fmaxf(bi.x, bj.x), 0.f);
        float h = fmaxf(fminf(bi.w, bj.w) - fmaxf(bi.y, bj.y), 0.f);
        float inter = w * h;
        float um = fmaxf((areai + carea[c]) - inter, 1e-8f);
        if (__fdiv_rn(inter, um) > 0.7f) bits |= 1ULL << c;
    }
}

// Row-pair register-blocked mask: 64 threads per block compute a 128-row x
// 64-col tile (2 rows/thread), amortizing column LDS + loop overhead.
// Tiles with cblk >= 2*rblk only (272 per image). Diagonal decomposition:
//   cblk==2rblk   : row0 from c=t+1, row1 empty (all j < i)
//   cblk==2rblk+1 : row0 full, row1 from c=t+1
//   cblk>=2rblk+2 : both rows full (fused unrolled loop)
__global__ void __launch_bounds__(64) k_mask() {
    int b = blockIdx.y;
    int t = threadIdx.x;
    int lin = blockIdx.x, rblk = 0;
    while (lin >= 32 - 2 * rblk) { lin -= 32 - 2 * rblk; rblk++; }
    int cblk = 2 * rblk + lin;
    int rb = rblk << 7, cb = cblk << 6;
    __shared__ float4 cbox[64];
    __shared__ float carea[64];
    {
        int j0 = cb + t;
        cbox[t] = (j0 < PRE) ? g_boxes[b][j0] : make_float4(-1.f, -1.f, -1.f, -1.f);
        carea[t] = (j0 < PRE) ? g_area[b][j0] : 0.f;
    }
    __syncthreads();
    int i0 = rb + t;          // always < PRE (max 1983)
    int i1 = rb + 64 + t;     // may exceed PRE
    float4 b0 = g_boxes[b][i0];
    float a0 = g_area[b][i0];
    if (cblk == 2 * rblk) {
        ull bits0 = 0ULL;
        iou_row(b0, a0, cbox, carea, t + 1, bits0);
        g_mask[b][i0][cblk] = bits0;
        return;
    }
    bool has1 = (i1 < PRE);
    float4 b1 = has1 ? g_boxes[b][i1] : make_float4(-1.f, -1.f, -1.f, -1.f);
    float a1 = has1 ? g_area[b][i1] : 0.f;
    ull bits0 = 0ULL, bits1 = 0ULL;
    if (cblk == 2 * rblk + 1) {
        iou_row(b0, a0, cbox, carea, 0, bits0);
        if (has1) iou_row(b1, a1, cbox, carea, t + 1, bits1);
    } else {
        // fused loop: one column load serves both rows
        ull amb0 = 0ULL, amb1 = 0ULL;
#pragma unroll 8
        for (int c = 0; c < 64; c++) {
            float4 bj = cbox[c];
            float aj = carea[c];
            float w0 = fmaxf(fminf(b0.z, bj.z) - fmaxf(b0.x, bj.x), 0.f);
            float h0 = fmaxf(fminf(b0.w, bj.w) - fmaxf(b0.y, bj.y), 0.f);
            float in0 = w0 * h0;
            float um0 = fmaxf((a0 + aj) - in0, 1e-8f);
            bool s0 = in0 > 0.70000210f * um0;
            bool q0 = (!s0) && (in0 >= 0.69999790f * um0);
            bits0 |= ((ull)s0) << c;
            amb0 |= ((ull)q0) << c;
            float w1 = fmaxf(fminf(b1.z, bj.z) - fmaxf(b1.x, bj.x), 0.f);
            float h1 = fmaxf(fminf(b1.w, bj.w) - fmaxf(b1.y, bj.y), 0.f);
            float in1 = w1 * h1;
            float um1 = fmaxf((a1 + aj) - in1, 1e-8f);
            bool s1 = in1 > 0.70000210f * um1;
            bool q1 = (!s1) && (in1 >= 0.69999790f * um1);
            bits1 |= ((ull)s1) << c;
            amb1 |= ((ull)q1) << c;
        }
        while (amb0) {
            int c = __ffsll(amb0) - 1;
            amb0 &= amb0 - 1;
            float4 bj = cbox[c];
            float w = fmaxf(fminf(b0.z, bj.z) - fmaxf(b0.x, bj.x), 0.f);
            float h = fmaxf(fminf(b0.w, bj.w) - fmaxf(b0.y, bj.y), 0.f);
            float inter = w * h;
            float um = fmaxf((a0 + carea[c]) - inter, 1e-8f);
            if (__fdiv_rn(inter, um) > 0.7f) bits0 |= 1ULL << c;
        }
        while (amb1) {
            int c = __ffsll(amb1) - 1;
            amb1 &= amb1 - 1;
            float4 bj = cbox[c];
            float w = fmaxf(fminf(b1.z, bj.z) - fmaxf(b1.x, bj.x), 0.f);
            float h = fmaxf(fminf(b1.w, bj.w) - fmaxf(b1.y, bj.y), 0.f);
            float inter = w * h;
            float um = fmaxf((a1 + carea[c]) - inter, 1e-8f);
            if (__fdiv_rn(inter, um) > 0.7f) bits1 |= 1ULL << c;
        }
    }
    g_mask[b][i0][cblk] = bits0;
    if (has1) g_mask[b][i1][cblk] = bits1;
}

__global__ void __launch_bounds__(256) k_scan(float4* __restrict__ out) {
    __shared__ ull ring[4][16][32];
    __shared__ int sel[POST];
    __shared__ int skc;
    int b = blockIdx.x;
    int tid = threadIdx.x;
    if (tid < 32) {
        int lane = tid;
        int nv = g_nvalid[b];
        int lo = lane * 64;
        ull rem;
        if (nv <= lo) rem = ~0ULL;
        else if (nv >= lo + 64) rem = 0ULL;
        else rem = (~0ULL) << (nv - lo);
        for (int nb = 0; nb < 3; nb++) {
#pragma unroll
            for (int q = 0; q < 16; q++)
                CP8(smaddr(&ring[nb][q][lane]), &g_mask[b][nb * 16 + q][lane]);
            CPCOMMIT();
        }
        int limit = (PRE < nv) ? PRE : nv;
        int kc = 0, w = 0;
        ull r = 0ULL;
        for (int bt = 0; bt < PRE / 16; bt++) {
            CPWAIT2();
            __syncwarp();
            int base = bt * 16;
            if (base >= limit) break;
            if ((base & 63) == 0) {
                w = base >> 6;
                r = __shfl_sync(0xffffffffu, rem, w);
            }
            ull m[16];
            unsigned keptm = 0;
            if (lane == 0) {
#pragma unroll
                for (int q = 0; q < 16; q++) m[q] = ring[bt & 3][q][w];
                int off = base & 63;
#pragma unroll
                for (int q = 0; q < 16; q++) {
                    int row = base + q;
                    bool keep = (row < limit) && !((r >> (off + q)) & 1ULL);
                    if (keep) {
                        if (kc < POST) sel[kc] = row;
                        kc++;
                        keptm |= 1u << q;
                        r |= m[q];
                    }
                }
            }
            keptm = __shfl_sync(0xffffffffu, keptm, 0);
            ull acc = 0ULL;
#pragma unroll
            for (int q = 0; q < 16; q++)
                if ((keptm >> q) & 1u) acc |= ring[bt & 3][q][lane];
            if (lane >= w) rem |= acc;
            kc = __shfl_sync(0xffffffffu, kc, 0);
            if (kc >= POST) break;
            int nb = bt + 3;
            if (nb < PRE / 16) {
#pragma unroll
                for (int q = 0; q < 16; q++)
                    CP8(smaddr(&ring[nb & 3][q][lane]), &g_mask[b][nb * 16 + q][lane]);
            }
            CPCOMMIT();
        }
        CPWAITALL();
        if (lane == 0) skc = (kc < POST) ? kc : POST;
    }
    __syncthreads();
    int kc = skc;
    for (int k = tid; k < POST; k += blockDim.x) {
        float4 v = make_float4(0.f, 0.f, 0.f, 0.f);
        if (k < kc) v = g_boxes[b][sel[k]];
        out[(size_t)b * POST + k] = v;
    }
}

extern "C" void kernel_launch(void* const* d_in, const int* in_sizes, int n_in,
                              void* d_out, int out_size) {
    const float* cls = (const float*)d_in[0];
    const float* reg = (const float*)d_in[1];
    const float* anchors = (const float*)d_in[2];
    float4* out = (float4*)d_out;

    k_hist<<<dim3(NBLK, BB), 256>>>(cls);
    k_cut<<<BB, 256>>>(cls);
    k_compact<<<dim3(NBLK, BB), 256>>>(cls);
    k_sortdecode<<<BB, 1024>>>(reg, anchors);
    k_mask<<<dim3(272, BB), 64>>>();
    k_scan<<<BB, 256>>>(out);
}

// round 9
// speedup vs baseline: 1.1117x; 1.0569x over previous
#include <cuda_runtime.h>
#include <math.h>

#define BB 16
#define NN 300000
#define NV 75000
#define NBLK 37
#define PRE 2000
#define POST 1000
#define CANDMAX 4096
#define MASKW 32
#define STAGE 1024

typedef unsigned long long ull;

__device__ unsigned g_phist[BB][NBLK][2048];
__device__ int g_cut[BB];
__device__ unsigned g_ccount[BB];
__device__ ull g_cand[BB][CANDMAX];
__device__ float4 g_boxes[BB][PRE];
__device__ float g_area[BB][PRE];
__device__ int g_nvalid[BB];
__device__ ull g_mask[BB][PRE][MASKW];

__device__ __forceinline__ unsigned keyf(float f) {
    unsigned u = __float_as_uint(f);
    return u ^ ((u >> 31) ? 0xFFFFFFFFu : 0x80000000u);
}

__device__ __forceinline__ unsigned smaddr(const void* p) {
    return (unsigned)__cvta_generic_to_shared(p);
}
#define CP8(dst, src) asm volatile("cp.async.ca.shared.global [%0], [%1], 8;" :: "r"(dst), "l"(src))
#define CPCOMMIT() asm volatile("cp.async.commit_group;")
#define CPWAIT2() asm volatile("cp.async.wait_group 2;")
#define CPWAITALL() asm volatile("cp.async.wait_all;")

__global__ void __launch_bounds__(256) k_hist(const float* __restrict__ cls) {
    __shared__ unsigned sh[2048];
    int b = blockIdx.y;
    int t = threadIdx.x;
    for (int i = t; i < 2048; i += 256) sh[i] = 0u;
    __syncthreads();
    const float4* __restrict__ p = (const float4*)(cls + (size_t)b * NN);
    int base = blockIdx.x * 2048;
    if (base + 2048 <= NV) {
        float4 v[8];
#pragma unroll
        for (int k = 0; k < 8; k++) v[k] = p[base + t + 256 * k];
#pragma unroll
        for (int k = 0; k < 8; k++) {
            unsigned kk[4] = {keyf(v[k].x), keyf(v[k].y), keyf(v[k].z), keyf(v[k].w)};
#pragma unroll
            for (int q = 0; q < 4; q++)
                if (kk[q] >= 0x80000000u) atomicAdd(&sh[(kk[q] >> 20) - 2048], 1u);
        }
    } else {
        for (int k = 0; k < 8; k++) {
            int id = base + t + 256 * k;
            if (id < NV) {
                float4 v = p[id];
                unsigned kk[4] = {keyf(v.x), keyf(v.y), keyf(v.z), keyf(v.w)};
#pragma unroll
                for (int q = 0; q < 4; q++)
                    if (kk[q] >= 0x80000000u) atomicAdd(&sh[(kk[q] >> 20) - 2048], 1u);
            }
        }
    }
    __syncthreads();
    for (int i = t; i < 2048; i += 256) g_phist[b][blockIdx.x][i] = sh[i];
}

__global__ void __launch_bounds__(256) k_cut(const float* __restrict__ cls) {
    __shared__ unsigned hist[2048];
    __shared__ unsigned csum[256];
    __shared__ int sneed;
    int b = blockIdx.x;
    int t = threadIdx.x;
    unsigned loc[8] = {0, 0, 0, 0, 0, 0, 0, 0};
    for (int blk = 0; blk < NBLK; blk++) {
#pragma unroll
        for (int q = 0; q < 8; q++) loc[q] += g_phist[b][blk][t * 8 + q];
    }
    unsigned s = 0;
#pragma unroll
    for (int q = 0; q < 8; q++) { hist[t * 8 + q] = loc[q]; s += loc[q]; }
    csum[t] = s;
    __syncthreads();
    if (t == 0) {
        g_ccount[b] = 0u;
        unsigned acc = 0;
        int found = 0;
        for (int c = 255; c >= 0; c--) {
            if (acc + csum[c] >= PRE) {
                for (int i = 7; i >= 0; i--) {
                    unsigned h = hist[c * 8 + i];
                    if (acc + h >= PRE) { g_cut[b] = 2048 + c * 8 + i; found = 1; break; }
                    acc += h;
                }
                break;
            }
            acc += csum[c];
        }
        sneed = !found;
        if (!found) g_cut[b] = 0;
    }
    __syncthreads();
    if (sneed) {  // cold fallback: full-range histogram by this one block
        __shared__ unsigned fh2[4096];
        for (int i = t; i < 4096; i += 256) fh2[i] = 0u;
        __syncthreads();
        const float4* __restrict__ p = (const float4*)(cls + (size_t)b * NN);
        for (int id = t; id < NV; id += 256) {
            float4 v = p[id];
            atomicAdd(&fh2[keyf(v.x) >> 20], 1u);
            atomicAdd(&fh2[keyf(v.y) >> 20], 1u);
            atomicAdd(&fh2[keyf(v.z) >> 20], 1u);
            atomicAdd(&fh2[keyf(v.w) >> 20], 1u);
        }
        __syncthreads();
        unsigned s2 = 0;
        for (int q = 0; q < 16; q++) s2 += fh2[t * 16 + q];
        csum[t] = s2;
        __syncthreads();
        if (t == 0) {
            unsigned acc = 0;
            for (int c = 255; c >= 0; c--) {
                if (acc + csum[c] >= PRE) {
                    for (int i = 15; i >= 0; i--) {
                        unsigned h = fh2[c * 16 + i];
                        if (acc + h >= PRE) { g_cut[b] = c * 16 + i; return; }
                        acc += h;
                    }
                    return;
                }
                acc += csum[c];
            }
            g_cut[b] = 0;
        }
    }
}

__global__ void __launch_bounds__(256) k_compact(const float* __restrict__ cls) {
    __shared__ ull stage[STAGE];
    __shared__ unsigned s_cnt, s_base;
    int b = blockIdx.y;
    int t = threadIdx.x;
    int cut = g_cut[b];
    if (t == 0) s_cnt = 0u;
    __syncthreads();
    const float4* __restrict__ p = (const float4*)(cls + (size_t)b * NN);
    int base = blockIdx.x * 2048;
    if (base + 2048 <= NV) {
        float4 v[8];
#pragma unroll
        for (int k = 0; k < 8; k++) v[k] = p[base + t + 256 * k];
#pragma unroll
        for (int k = 0; k < 8; k++) {
            int id = base + t + 256 * k;
            unsigned kk[4] = {keyf(v[k].x), keyf(v[k].y), keyf(v[k].z), keyf(v[k].w)};
#pragma unroll
            for (int q = 0; q < 4; q++) {
                if ((int)(kk[q] >> 20) >= cut) {
                    unsigned r = atomicAdd(&s_cnt, 1u);
                    if (r < STAGE)
                        stage[r] = ((ull)kk[q] << 32) | (unsigned)(~(4 * id + q));
                }
            }
        }
    } else {
        for (int k = 0; k < 8; k++) {
            int id = base + t + 256 * k;
            if (id < NV) {
                float4 v = p[id];
                unsigned kk[4] = {keyf(v.x), keyf(v.y), keyf(v.z), keyf(v.w)};
#pragma unroll
                for (int q = 0; q < 4; q++) {
                    if ((int)(kk[q] >> 20) >= cut) {
                        unsigned r = atomicAdd(&s_cnt, 1u);
                        if (r < STAGE)
                            stage[r] = ((ull)kk[q] << 32) | (unsigned)(~(4 * id + q));
                    }
                }
            }
        }
    }
    __syncthreads();
    if (t == 0) {
        unsigned c = s_cnt < STAGE ? s_cnt : STAGE;
        s_base = atomicAdd(&g_ccount[b], c);
    }
    __syncthreads();
    unsigned c = s_cnt < STAGE ? s_cnt : STAGE;
    for (unsigned r = t; r < c; r += 256) {
        unsigned pos = s_base + r;
        if (pos < CANDMAX) g_cand[b][pos] = stage[r];
    }
}

#define CSW(a, c, d) { if ((d) ? ((a) < (c)) : ((a) > (c))) { ull _t = (a); (a) = (c); (c) = _t; } }
#define KM(e, o) ((kmax) ? ((e) > (o) ? (e) : (o)) : ((e) < (o) ? (e) : (o)))
#define SHFLP() { \
    int m = j >> 2; \
    bool kmax = (desc != ((tid & m) != 0)); \
    ull o0 = __shfl_xor_sync(0xffffffffu, e0, m); \
    ull o1 = __shfl_xor_sync(0xffffffffu, e1, m); \
    ull o2 = __shfl_xor_sync(0xffffffffu, e2, m); \
    ull o3 = __shfl_xor_sync(0xffffffffu, e3, m); \
    e0 = KM(e0, o0); e1 = KM(e1, o1); e2 = KM(e2, o2); e3 = KM(e3, o3); }

// Fine-cut refinement (bits 12..19 of the key) computed in-prologue from the
// already-loaded candidates; filter to a provable top-PRE superset (<=2048),
// then sort 2048 instead of 4096. Fallback: full 4096 sort.
__global__ void __launch_bounds__(1024)
k_sortdecode(const float* __restrict__ reg, const float* __restrict__ anchors) {
    __shared__ ull sk[CANDMAX];
    __shared__ int swsum[32];
    __shared__ unsigned fh[256];
    __shared__ int s_fcut, s_kept;
    int b = blockIdx.x;
    int tid = threadIdx.x;
    int lane = tid & 31, wid = tid >> 5;
    unsigned n = g_ccount[b];
    if (n > CANDMAX) n = CANDMAX;
    int cut = g_cut[b];
    int b4 = 4 * tid;
    // load candidates once
    ull c0 = (b4 + 0 < (int)n) ? g_cand[b][b4 + 0] : 0ULL;
    ull c1 = (b4 + 1 < (int)n) ? g_cand[b][b4 + 1] : 0ULL;
    ull c2 = (b4 + 2 < (int)n) ? g_cand[b][b4 + 2] : 0ULL;
    ull c3 = (b4 + 3 < (int)n) ? g_cand[b][b4 + 3] : 0ULL;
    if (tid < 256) fh[tid] = 0u;
    __syncthreads();
#define FH(ci, off) { if (b4 + off < (int)n) { unsigned key = (unsigned)((ci) >> 32); \
        if ((int)(key >> 20) == cut) atomicAdd(&fh[(key >> 12) & 0xFF], 1u); } }
    FH(c0, 0) FH(c1, 1) FH(c2, 2) FH(c3, 3)
#undef FH
    __syncthreads();
    if (tid == 0) {
        unsigned tie = 0;
        for (int f = 0; f < 256; f++) tie += fh[f];
        int nab = (int)n - (int)tie;
        int acc = 0, fcut = 0, kept = (int)n;
        for (int f = 255; f >= 0; f--) {
            if (nab + acc + (int)fh[f] >= PRE) { fcut = f; kept = nab + acc + (int)fh[f]; break; }
            acc += (int)fh[f];
        }
        s_fcut = fcut;
        s_kept = kept;
    }
    __syncthreads();
    int kept = s_kept, fcut = s_fcut;
    ull e0 = 0, e1 = 0, e2 = 0, e3 = 0;
    if (kept <= 2048) {
        // filter + stable compact into sk[0..kept), sort 2048 (512 act threads)
        int p0 = 0, p1 = 0, p2 = 0, p3 = 0;
#define PRED(ci, pi, off) { if (b4 + off < (int)n) { unsigned key = (unsigned)((ci) >> 32); \
        pi = ((int)(key >> 20) > cut) || ((int)((key >> 12) & 0xFF) >= fcut); } }
        PRED(c0, p0, 0) PRED(c1, p1, 1) PRED(c2, p2, 2) PRED(c3, p3, 3)
#undef PRED
        int cnt = p0 + p1 + p2 + p3;
        int v = cnt;
        for (int o = 1; o < 32; o <<= 1) {
            int t2 = __shfl_up_sync(0xffffffffu, v, o);
            if (lane >= o) v += t2;
        }
        if (lane == 31) swsum[wid] = v;
        __syncthreads();
        if (wid == 0) {
            int x = swsum[lane];
            for (int o = 1; o < 32; o <<= 1) {
                int t2 = __shfl_up_sync(0xffffffffu, x, o);
                if (lane >= o) x += t2;
            }
            swsum[lane] = x;
        }
        __syncthreads();
        int excl = v - cnt + (wid ? swsum[wid - 1] : 0);
        sk[tid] = 0ULL;
        sk[tid + 1024] = 0ULL;
        __syncthreads();
        int pos = excl;
        if (p0) sk[pos++] = c0;
        if (p1) sk[pos++] = c1;
        if (p2) sk[pos++] = c2;
        if (p3) sk[pos++] = c3;
        __syncthreads();
        bool act = (tid < 512);
        if (act) {
            e0 = sk[b4]; e1 = sk[b4 + 1]; e2 = sk[b4 + 2]; e3 = sk[b4 + 3];
            CSW(e0, e1, true);
            CSW(e2, e3, false);
        }
        for (int k = 4; k <= 2048; k <<= 1) {
            bool desc = ((b4 & k) == 0);
            for (int j = k >> 1; j >= 128; j >>= 1) {
                if (act) { sk[b4] = e0; sk[b4 + 1] = e1; sk[b4 + 2] = e2; sk[b4 + 3] = e3; }
                __syncthreads();
                if (act) {
                    int m = j >> 2;
                    int pt = 4 * (tid ^ m);
                    bool kmax = (desc != ((tid & m) != 0));
                    ull o0 = sk[pt], o1 = sk[pt + 1], o2 = sk[pt + 2], o3 = sk[pt + 3];
                    e0 = KM(e0, o0); e1 = KM(e1, o1); e2 = KM(e2, o2); e3 = KM(e3, o3);
                }
                __syncthreads();
            }
            if (act) {
                int jstart = (k >> 1) < 64 ? (k >> 1) : 64;
                for (int j = jstart; j >= 4; j >>= 1) SHFLP()
                CSW(e0, e2, desc); CSW(e1, e3, desc);
                CSW(e0, e1, desc); CSW(e2, e3, desc);
            }
        }
        if (act) { sk[b4] = e0; sk[b4 + 1] = e1; sk[b4 + 2] = e2; sk[b4 + 3] = e3; }
        __syncthreads();
    } else {
        // fallback: full 4096 sort
        e0 = c0; e1 = c1; e2 = c2; e3 = c3;
        CSW(e0, e1, true);
        CSW(e2, e3, false);
        for (int k = 4; k <= CANDMAX; k <<= 1) {
            bool desc = ((b4 & k) == 0);
            for (int j = k >> 1; j >= 128; j >>= 1) {
                sk[b4] = e0; sk[b4 + 1] = e1; sk[b4 + 2] = e2; sk[b4 + 3] = e3;
                __syncthreads();
                int m = j >> 2;
                int pt = 4 * (tid ^ m);
                bool kmax = (desc != ((tid & m) != 0));
                ull o0 = sk[pt], o1 = sk[pt + 1], o2 = sk[pt + 2], o3 = sk[pt + 3];
                e0 = KM(e0, o0); e1 = KM(e1, o1); e2 = KM(e2, o2); e3 = KM(e3, o3);
                __syncthreads();
            }
            int jstart = (k >> 1) < 64 ? (k >> 1) : 64;
            for (int j = jstart; j >= 4; j >>= 1) SHFLP()
            CSW(e0, e2, desc); CSW(e1, e3, desc);
            CSW(e0, e1, desc); CSW(e2, e3, desc);
        }
        sk[b4] = e0; sk[b4 + 1] = e1; sk[b4 + 2] = e2; sk[b4 + 3] = e3;
        __syncthreads();
    }
    // decode + stable valid-first partition
    float4 box[2];
    int val[2];
#pragma unroll
    for (int q = 0; q < 2; q++) {
        int e = 2 * tid + q;
        val[q] = 0;
        box[q] = make_float4(0.f, 0.f, 0.f, 0.f);
        if (e < PRE) {
            unsigned idx = ~(unsigned)(sk[e] & 0xFFFFFFFFULL);
            const float* a = anchors + ((size_t)b * NN + idx) * 4;
            const float* r = reg + ((size_t)b * NN + idx) * 4;
            float a0 = a[0], a1 = a[1], a2 = a[2], a3 = a[3];
            float dx = r[0], dy = r[1], dw = r[2], dh = r[3];
            float aw = a2 - a0, ah = a3 - a1;
            float acx = a0 + 0.5f * aw, acy = a1 + 0.5f * ah;
            float pcx = dx * aw + acx, pcy = dy * ah + acy;
            float pw = expf(dw) * aw, ph = expf(dh) * ah;
            float x1 = pcx - 0.5f * pw, y1 = pcy - 0.5f * ph;
            float x2 = pcx + 0.5f * pw, y2 = pcy + 0.5f * ph;
            x1 = fminf(fmaxf(x1, 0.f), 1333.f);
            y1 = fminf(fmaxf(y1, 0.f), 800.f);
            x2 = fminf(fmaxf(x2, 0.f), 1333.f);
            y2 = fminf(fmaxf(y2, 0.f), 800.f);
            float w = x2 - x1, h = y2 - y1;
            val[q] = (w >= 0.001f && h >= 0.001f) ? 1 : 0;
            box[q] = make_float4(x1, y1, x2, y2);
        }
    }
    int pairsum = val[0] + val[1];
    int v = pairsum;
    for (int o = 1; o < 32; o <<= 1) {
        int t2 = __shfl_up_sync(0xffffffffu, v, o);
        if (lane >= o) v += t2;
    }
    if (lane == 31) swsum[wid] = v;
    __syncthreads();
    if (wid == 0) {
        int x = swsum[lane];
        for (int o = 1; o < 32; o <<= 1) {
            int t2 = __shfl_up_sync(0xffffffffu, x, o);
            if (lane >= o) x += t2;
        }
        swsum[lane] = x;
    }
    __syncthreads();
    int incl = v + (wid ? swsum[wid - 1] : 0);
    int excl = incl - pairsum;
    int nv = swsum[31];
    int ea = 2 * tid, eb = 2 * tid + 1;
    int rank0 = excl;
    int rank1 = excl + val[0];
    int pos0 = val[0] ? rank0 : nv + (ea - rank0);
    int pos1 = val[1] ? rank1 : nv + (eb - rank1);
    if (ea < PRE) {
        g_boxes[b][pos0] = box[0];
        g_area[b][pos0] = (box[0].z - box[0].x) * (box[0].w - box[0].y);
    }
    if (eb < PRE) {
        g_boxes[b][pos1] = box[1];
        g_area[b][pos1] = (box[1].z - box[1].x) * (box[1].w - box[1].y);
    }
    if (tid == 0) g_nvalid[b] = nv;
}

// R6 single-row mask (measured best): 528 upper-triangle tiles per image.
__global__ void __launch_bounds__(64) k_mask() {
    int b = blockIdx.y;
    int t = threadIdx.x;
    int lin = blockIdx.x, rblk = 0;
    while (lin >= 32 - rblk) { lin -= 32 - rblk; rblk++; }
    int cblk = rblk + lin;
    int rb = rblk << 6, cb = cblk << 6;
    __shared__ float4 cbox[64];
    __shared__ float carea[64];
    {
        int j0 = cb + t;
        cbox[t] = (j0 < PRE) ? g_boxes[b][j0] : make_float4(-1.f, -1.f, -1.f, -1.f);
        carea[t] = (j0 < PRE) ? g_area[b][j0] : 0.f;
    }
    __syncthreads();
    int i = rb + t;
    if (i >= PRE) return;
    float4 bi = g_boxes[b][i];
    float areai = g_area[b][i];
    ull bits = 0ULL, amb = 0ULL;
    int c0 = (cblk == rblk) ? (t + 1) : 0;
#pragma unroll 8
    for (int c = c0; c < 64; c++) {
        float4 bj = cbox[c];
        float w = fmaxf(fminf(bi.z, bj.z) - fmaxf(bi.x, bj.x), 0.f);
        float h = fmaxf(fminf(bi.w, bj.w) - fmaxf(bi.y, bj.y), 0.f);
        float inter = w * h;
        float um = fmaxf((areai + carea[c]) - inter, 1e-8f);
        bool s1 = inter > 0.70000210f * um;
        bool a1 = (!s1) && (inter >= 0.69999790f * um);
        bits |= ((ull)s1) << c;
        amb |= ((ull)a1) << c;
    }
    while (amb) {
        int c = __ffsll(amb) - 1;
        amb &= amb - 1;
        float4 bj = cbox[c];
        float w = fmaxf(fminf(bi.z, bj.z) - fmaxf(bi.x, bj.x), 0.f);
        float h = fmaxf(fminf(bi.w, bj.w) - fmaxf(bi.y, bj.y), 0.f);
        float inter = w * h;
        float um = fmaxf((areai + carea[c]) - inter, 1e-8f);
        if (__fdiv_rn(inter, um) > 0.7f) bits |= 1ULL << c;
    }
    g_mask[b][i][cblk] = bits;
}

__global__ void __launch_bounds__(256) k_scan(float4* __restrict__ out) {
    __shared__ ull ring[4][16][32];
    __shared__ int sel[POST];
    __shared__ int skc;
    int b = blockIdx.x;
    int tid = threadIdx.x;
    if (tid < 32) {
        int lane = tid;
        int nv = g_nvalid[b];
        int lo = lane * 64;
        ull rem;
        if (nv <= lo) rem = ~0ULL;
        else if (nv >= lo + 64) rem = 0ULL;
        else rem = (~0ULL) << (nv - lo);
        for (int nb = 0; nb < 3; nb++) {
#pragma unroll
            for (int q = 0; q < 16; q++)
                CP8(smaddr(&ring[nb][q][lane]), &g_mask[b][nb * 16 + q][lane]);
            CPCOMMIT();
        }
        int limit = (PRE < nv) ? PRE : nv;
        int kc = 0, w = 0;
        ull r = 0ULL;
        for (int bt = 0; bt < PRE / 16; bt++) {
            CPWAIT2();
            __syncwarp();
            int base = bt * 16;
            if (base >= limit) break;
            if ((base & 63) == 0) {
                w = base >> 6;
                r = __shfl_sync(0xffffffffu, rem, w);
            }
            ull m[16];
            unsigned keptm = 0;
            if (lane == 0) {
#pragma unroll
                for (int q = 0; q < 16; q++) m[q] = ring[bt & 3][q][w];
                int off = base & 63;
#pragma unroll
                for (int q = 0; q < 16; q++) {
                    int row = base + q;
                    bool keep = (row < limit) && !((r >> (off + q)) & 1ULL);
                    if (keep) {
                        if (kc < POST) sel[kc] = row;
                        kc++;
                        keptm |= 1u << q;
                        r |= m[q];
                    }
                }
            }
            keptm = __shfl_sync(0xffffffffu, keptm, 0);
            ull acc = 0ULL;
#pragma unroll
            for (int q = 0; q < 16; q++)
                if ((keptm >> q) & 1u) acc |= ring[bt & 3][q][lane];
            if (lane >= w) rem |= acc;
            kc = __shfl_sync(0xffffffffu, kc, 0);
            if (kc >= POST) break;
            int nb = bt + 3;
            if (nb < PRE / 16) {
#pragma unroll
                for (int q = 0; q < 16; q++)
                    CP8(smaddr(&ring[nb & 3][q][lane]), &g_mask[b][nb * 16 + q][lane]);
            }
            CPCOMMIT();
        }
        CPWAITALL();
        if (lane == 0) skc = (kc < POST) ? kc : POST;
    }
    __syncthreads();
    int kc = skc;
    for (int k = tid; k < POST; k += blockDim.x) {
        float4 v = make_float4(0.f, 0.f, 0.f, 0.f);
        if (k < kc) v = g_boxes[b][sel[k]];
        out[(size_t)b * POST + k] = v;
    }
}

extern "C" void kernel_launch(void* const* d_in, const int* in_sizes, int n_in,
                              void* d_out, int out_size) {
    const float* cls = (const float*)d_in[0];
    const float* reg = (const float*)d_in[1];
    const float* anchors = (const float*)d_in[2];
    float4* out = (float4*)d_out;

    k_hist<<<dim3(NBLK, BB), 256>>>(cls);
    k_cut<<<BB, 256>>>(cls);
    k_compact<<<dim3(NBLK, BB), 256>>>(cls);
    k_sortdecode<<<BB, 1024>>>(reg, anchors);
    k_mask<<<dim3(528, BB), 64>>>();
    k_scan<<<BB, 256>>>(out);
}

// round 10
// speedup vs baseline: 1.1281x; 1.0148x over previous
#include <cuda_runtime.h>
#include <math.h>

#define BB 16
#define NN 300000
#define NV 75000
#define NBLK 37
#define PRE 2000
#define POST 1000
#define CANDMAX 4096
#define MASKW 32
#define STAGE 1024

typedef unsigned long long ull;

__device__ unsigned g_phist[BB][NBLK][2048];
__device__ int g_cut[BB];
__device__ unsigned g_ccount[BB];
__device__ ull g_cand[BB][CANDMAX];
__device__ float4 g_boxes[BB][PRE];
__device__ float g_area[BB][PRE];
__device__ int g_nvalid[BB];
__device__ ull g_mask[BB][PRE][MASKW];

__device__ __forceinline__ unsigned keyf(float f) {
    unsigned u = __float_as_uint(f);
    return u ^ ((u >> 31) ? 0xFFFFFFFFu : 0x80000000u);
}

__device__ __forceinline__ unsigned smaddr(const void* p) {
    return (unsigned)__cvta_generic_to_shared(p);
}
#define CP8(dst, src) asm volatile("cp.async.ca.shared.global [%0], [%1], 8;" :: "r"(dst), "l"(src))
#define CPCOMMIT() asm volatile("cp.async.commit_group;")
#define CPWAIT2() asm volatile("cp.async.wait_group 2;")
#define CPWAITALL() asm volatile("cp.async.wait_all;")

__global__ void __launch_bounds__(256) k_hist(const float* __restrict__ cls) {
    __shared__ unsigned sh[2048];
    int b = blockIdx.y;
    int t = threadIdx.x;
    for (int i = t; i < 2048; i += 256) sh[i] = 0u;
    __syncthreads();
    const float4* __restrict__ p = (const float4*)(cls + (size_t)b * NN);
    int base = blockIdx.x * 2048;
    if (base + 2048 <= NV) {
        float4 v[8];
#pragma unroll
        for (int k = 0; k < 8; k++) v[k] = p[base + t + 256 * k];
#pragma unroll
        for (int k = 0; k < 8; k++) {
            unsigned kk[4] = {keyf(v[k].x), keyf(v[k].y), keyf(v[k].z), keyf(v[k].w)};
#pragma unroll
            for (int q = 0; q < 4; q++)
                if (kk[q] >= 0x80000000u) atomicAdd(&sh[(kk[q] >> 20) - 2048], 1u);
        }
    } else {
        for (int k = 0; k < 8; k++) {
            int id = base + t + 256 * k;
            if (id < NV) {
                float4 v = p[id];
                unsigned kk[4] = {keyf(v.x), keyf(v.y), keyf(v.z), keyf(v.w)};
#pragma unroll
                for (int q = 0; q < 4; q++)
                    if (kk[q] >= 0x80000000u) atomicAdd(&sh[(kk[q] >> 20) - 2048], 1u);
            }
        }
    }
    __syncthreads();
    for (int i = t; i < 2048; i += 256) g_phist[b][blockIdx.x][i] = sh[i];
}

__global__ void __launch_bounds__(256) k_cut(const float* __restrict__ cls) {
    __shared__ unsigned hist[2048];
    __shared__ unsigned csum[256];
    __shared__ int sneed;
    int b = blockIdx.x;
    int t = threadIdx.x;
    unsigned loc[8] = {0, 0, 0, 0, 0, 0, 0, 0};
    for (int blk = 0; blk < NBLK; blk++) {
#pragma unroll
        for (int q = 0; q < 8; q++) loc[q] += g_phist[b][blk][t * 8 + q];
    }
    unsigned s = 0;
#pragma unroll
    for (int q = 0; q < 8; q++) { hist[t * 8 + q] = loc[q]; s += loc[q]; }
    csum[t] = s;
    __syncthreads();
    if (t == 0) {
        g_ccount[b] = 0u;
        unsigned acc = 0;
        int found = 0;
        for (int c = 255; c >= 0; c--) {
            if (acc + csum[c] >= PRE) {
                for (int i = 7; i >= 0; i--) {
                    unsigned h = hist[c * 8 + i];
                    if (acc + h >= PRE) { g_cut[b] = 2048 + c * 8 + i; found = 1; break; }
                    acc += h;
                }
                break;
            }
            acc += csum[c];
        }
        sneed = !found;
        if (!found) g_cut[b] = 0;
    }
    __syncthreads();
    if (sneed) {  // cold fallback: full-range histogram by this one block
        __shared__ unsigned fh2[4096];
        for (int i = t; i < 4096; i += 256) fh2[i] = 0u;
        __syncthreads();
        const float4* __restrict__ p = (const float4*)(cls + (size_t)b * NN);
        for (int id = t; id < NV; id += 256) {
            float4 v = p[id];
            atomicAdd(&fh2[keyf(v.x) >> 20], 1u);
            atomicAdd(&fh2[keyf(v.y) >> 20], 1u);
            atomicAdd(&fh2[keyf(v.z) >> 20], 1u);
            atomicAdd(&fh2[keyf(v.w) >> 20], 1u);
        }
        __syncthreads();
        unsigned s2 = 0;
        for (int q = 0; q < 16; q++) s2 += fh2[t * 16 + q];
        csum[t] = s2;
        __syncthreads();
        if (t == 0) {
            unsigned acc = 0;
            for (int c = 255; c >= 0; c--) {
                if (acc + csum[c] >= PRE) {
                    for (int i = 15; i >= 0; i--) {
                        unsigned h = fh2[c * 16 + i];
                        if (acc + h >= PRE) { g_cut[b] = c * 16 + i; return; }
                        acc += h;
                    }
                    return;
                }
                acc += csum[c];
            }
            g_cut[b] = 0;
        }
    }
}

__global__ void __launch_bounds__(256) k_compact(const float* __restrict__ cls) {
    __shared__ ull stage[STAGE];
    __shared__ unsigned s_cnt, s_base;
    int b = blockIdx.y;
    int t = threadIdx.x;
    int cut = g_cut[b];
    if (t == 0) s_cnt = 0u;
    __syncthreads();
    const float4* __restrict__ p = (const float4*)(cls + (size_t)b * NN);
    int base = blockIdx.x * 2048;
    if (base + 2048 <= NV) {
        float4 v[8];
#pragma unroll
        for (int k = 0; k < 8; k++) v[k] = p[base + t + 256 * k];
#pragma unroll
        for (int k = 0; k < 8; k++) {
            int id = base + t + 256 * k;
            unsigned kk[4] = {keyf(v[k].x), keyf(v[k].y), keyf(v[k].z), keyf(v[k].w)};
#pragma unroll
            for (int q = 0; q < 4; q++) {
                if ((int)(kk[q] >> 20) >= cut) {
                    unsigned r = atomicAdd(&s_cnt, 1u);
                    if (r < STAGE)
                        stage[r] = ((ull)kk[q] << 32) | (unsigned)(~(4 * id + q));
                }
            }
        }
    } else {
        for (int k = 0; k < 8; k++) {
            int id = base + t + 256 * k;
            if (id < NV) {
                float4 v = p[id];
                unsigned kk[4] = {keyf(v.x), keyf(v.y), keyf(v.z), keyf(v.w)};
#pragma unroll
                for (int q = 0; q < 4; q++) {
                    if ((int)(kk[q] >> 20) >= cut) {
                        unsigned r = atomicAdd(&s_cnt, 1u);
                        if (r < STAGE)
                            stage[r] = ((ull)kk[q] << 32) | (unsigned)(~(4 * id + q));
                    }
                }
            }
        }
    }
    __syncthreads();
    if (t == 0) {
        unsigned c = s_cnt < STAGE ? s_cnt : STAGE;
        s_base = atomicAdd(&g_ccount[b], c);
    }
    __syncthreads();
    unsigned c = s_cnt < STAGE ? s_cnt : STAGE;
    for (unsigned r = t; r < c; r += 256) {
        unsigned pos = s_base + r;
        if (pos < CANDMAX) g_cand[b][pos] = stage[r];
    }
}

#define CSW(a, c, d) { if ((d) ? ((a) < (c)) : ((a) > (c))) { ull _t = (a); (a) = (c); (c) = _t; } }
#define KM(e, o) ((kmax) ? ((e) > (o) ? (e) : (o)) : ((e) < (o) ? (e) : (o)))
#define SHFLP() { \
    int m = j >> 2; \
    bool kmax = (desc != ((tid & m) != 0)); \
    ull o0 = __shfl_xor_sync(0xffffffffu, e0, m); \
    ull o1 = __shfl_xor_sync(0xffffffffu, e1, m); \
    ull o2 = __shfl_xor_sync(0xffffffffu, e2, m); \
    ull o3 = __shfl_xor_sync(0xffffffffu, e3, m); \
    e0 = KM(e0, o0); e1 = KM(e1, o1); e2 = KM(e2, o2); e3 = KM(e3, o3); }

__global__ void __launch_bounds__(1024)
k_sortdecode(const float* __restrict__ reg, const float* __restrict__ anchors) {
    __shared__ ull sk[CANDMAX];
    __shared__ int swsum[32];
    __shared__ unsigned fh[256];
    __shared__ int s_fcut, s_kept;
    int b = blockIdx.x;
    int tid = threadIdx.x;
    int lane = tid & 31, wid = tid >> 5;
    unsigned n = g_ccount[b];
    if (n > CANDMAX) n = CANDMAX;
    int cut = g_cut[b];
    int b4 = 4 * tid;
    ull c0 = (b4 + 0 < (int)n) ? g_cand[b][b4 + 0] : 0ULL;
    ull c1 = (b4 + 1 < (int)n) ? g_cand[b][b4 + 1] : 0ULL;
    ull c2 = (b4 + 2 < (int)n) ? g_cand[b][b4 + 2] : 0ULL;
    ull c3 = (b4 + 3 < (int)n) ? g_cand[b][b4 + 3] : 0ULL;
    if (tid < 256) fh[tid] = 0u;
    __syncthreads();
#define FH(ci, off) { if (b4 + off < (int)n) { unsigned key = (unsigned)((ci) >> 32); \
        if ((int)(key >> 20) == cut) atomicAdd(&fh[(key >> 12) & 0xFF], 1u); } }
    FH(c0, 0) FH(c1, 1) FH(c2, 2) FH(c3, 3)
#undef FH
    __syncthreads();
    if (tid == 0) {
        unsigned tie = 0;
        for (int f = 0; f < 256; f++) tie += fh[f];
        int nab = (int)n - (int)tie;
        int acc = 0, fcut = 0, kept = (int)n;
        for (int f = 255; f >= 0; f--) {
            if (nab + acc + (int)fh[f] >= PRE) { fcut = f; kept = nab + acc + (int)fh[f]; break; }
            acc += (int)fh[f];
        }
        s_fcut = fcut;
        s_kept = kept;
    }
    __syncthreads();
    int kept = s_kept, fcut = s_fcut;
    ull e0 = 0, e1 = 0, e2 = 0, e3 = 0;
    if (kept <= 2048) {
        int p0 = 0, p1 = 0, p2 = 0, p3 = 0;
#define PRED(ci, pi, off) { if (b4 + off < (int)n) { unsigned key = (unsigned)((ci) >> 32); \
        pi = ((int)(key >> 20) > cut) || ((int)((key >> 12) & 0xFF) >= fcut); } }
        PRED(c0, p0, 0) PRED(c1, p1, 1) PRED(c2, p2, 2) PRED(c3, p3, 3)
#undef PRED
        int cnt = p0 + p1 + p2 + p3;
        int v = cnt;
        for (int o = 1; o < 32; o <<= 1) {
            int t2 = __shfl_up_sync(0xffffffffu, v, o);
            if (lane >= o) v += t2;
        }
        if (lane == 31) swsum[wid] = v;
        __syncthreads();
        if (wid == 0) {
            int x = swsum[lane];
            for (int o = 1; o < 32; o <<= 1) {
                int t2 = __shfl_up_sync(0xffffffffu, x, o);
                if (lane >= o) x += t2;
            }
            swsum[lane] = x;
        }
        __syncthreads();
        int excl = v - cnt + (wid ? swsum[wid - 1] : 0);
        sk[tid] = 0ULL;
        sk[tid + 1024] = 0ULL;
        __syncthreads();
        int pos = excl;
        if (p0) sk[pos++] = c0;
        if (p1) sk[pos++] = c1;
        if (p2) sk[pos++] = c2;
        if (p3) sk[pos++] = c3;
        __syncthreads();
        bool act = (tid < 512);
        if (act) {
            e0 = sk[b4]; e1 = sk[b4 + 1]; e2 = sk[b4 + 2]; e3 = sk[b4 + 3];
            CSW(e0, e1, true);
            CSW(e2, e3, false);
        }
        for (int k = 4; k <= 2048; k <<= 1) {
            bool desc = ((b4 & k) == 0);
            for (int j = k >> 1; j >= 128; j >>= 1) {
                if (act) { sk[b4] = e0; sk[b4 + 1] = e1; sk[b4 + 2] = e2; sk[b4 + 3] = e3; }
                __syncthreads();
                if (act) {
                    int m = j >> 2;
                    int pt = 4 * (tid ^ m);
                    bool kmax = (desc != ((tid & m) != 0));
                    ull o0 = sk[pt], o1 = sk[pt + 1], o2 = sk[pt + 2], o3 = sk[pt + 3];
                    e0 = KM(e0, o0); e1 = KM(e1, o1); e2 = KM(e2, o2); e3 = KM(e3, o3);
                }
                __syncthreads();
            }
            if (act) {
                int jstart = (k >> 1) < 64 ? (k >> 1) : 64;
                for (int j = jstart; j >= 4; j >>= 1) SHFLP()
                CSW(e0, e2, desc); CSW(e1, e3, desc);
                CSW(e0, e1, desc); CSW(e2, e3, desc);
            }
        }
        if (act) { sk[b4] = e0; sk[b4 + 1] = e1; sk[b4 + 2] = e2; sk[b4 + 3] = e3; }
        __syncthreads();
    } else {
        e0 = c0; e1 = c1; e2 = c2; e3 = c3;
        CSW(e0, e1, true);
        CSW(e2, e3, false);
        for (int k = 4; k <= CANDMAX; k <<= 1) {
            bool desc = ((b4 & k) == 0);
            for (int j = k >> 1; j >= 128; j >>= 1) {
                sk[b4] = e0; sk[b4 + 1] = e1; sk[b4 + 2] = e2; sk[b4 + 3] = e3;
                __syncthreads();
                int m = j >> 2;
                int pt = 4 * (tid ^ m);
                bool kmax = (desc != ((tid & m) != 0));
                ull o0 = sk[pt], o1 = sk[pt + 1], o2 = sk[pt + 2], o3 = sk[pt + 3];
                e0 = KM(e0, o0); e1 = KM(e1, o1); e2 = KM(e2, o2); e3 = KM(e3, o3);
                __syncthreads();
            }
            int jstart = (k >> 1) < 64 ? (k >> 1) : 64;
            for (int j = jstart; j >= 4; j >>= 1) SHFLP()
            CSW(e0, e2, desc); CSW(e1, e3, desc);
            CSW(e0, e1, desc); CSW(e2, e3, desc);
        }
        sk[b4] = e0; sk[b4 + 1] = e1; sk[b4 + 2] = e2; sk[b4 + 3] = e3;
        __syncthreads();
    }
    float4 box[2];
    int val[2];
#pragma unroll
    for (int q = 0; q < 2; q++) {
        int e = 2 * tid + q;
        val[q] = 0;
        box[q] = make_float4(0.f, 0.f, 0.f, 0.f);
        if (e < PRE) {
            unsigned idx = ~(unsigned)(sk[e] & 0xFFFFFFFFULL);
            const float* a = anchors + ((size_t)b * NN + idx) * 4;
            const float* r = reg + ((size_t)b * NN + idx) * 4;
            float a0 = a[0], a1 = a[1], a2 = a[2], a3 = a[3];
            float dx = r[0], dy = r[1], dw = r[2], dh = r[3];
            float aw = a2 - a0, ah = a3 - a1;
            float acx = a0 + 0.5f * aw, acy = a1 + 0.5f * ah;
            float pcx = dx * aw + acx, pcy = dy * ah + acy;
            float pw = expf(dw) * aw, ph = expf(dh) * ah;
            float x1 = pcx - 0.5f * pw, y1 = pcy - 0.5f * ph;
            float x2 = pcx + 0.5f * pw, y2 = pcy + 0.5f * ph;
            x1 = fminf(fmaxf(x1, 0.f), 1333.f);
            y1 = fminf(fmaxf(y1, 0.f), 800.f);
            x2 = fminf(fmaxf(x2, 0.f), 1333.f);
            y2 = fminf(fmaxf(y2, 0.f), 800.f);
            float w = x2 - x1, h = y2 - y1;
            val[q] = (w >= 0.001f && h >= 0.001f) ? 1 : 0;
            box[q] = make_float4(x1, y1, x2, y2);
        }
    }
    int pairsum = val[0] + val[1];
    int v = pairsum;
    for (int o = 1; o < 32; o <<= 1) {
        int t2 = __shfl_up_sync(0xffffffffu, v, o);
        if (lane >= o) v += t2;
    }
    if (lane == 31) swsum[wid] = v;
    __syncthreads();
    if (wid == 0) {
        int x = swsum[lane];
        for (int o = 1; o < 32; o <<= 1) {
            int t2 = __shfl_up_sync(0xffffffffu, x, o);
            if (lane >= o) x += t2;
        }
        swsum[lane] = x;
    }
    __syncthreads();
    int incl = v + (wid ? swsum[wid - 1] : 0);
    int excl = incl - pairsum;
    int nv = swsum[31];
    int ea = 2 * tid, eb = 2 * tid + 1;
    int rank0 = excl;
    int rank1 = excl + val[0];
    int pos0 = val[0] ? rank0 : nv + (ea - rank0);
    int pos1 = val[1] ? rank1 : nv + (eb - rank1);
    if (ea < PRE) {
        g_boxes[b][pos0] = box[0];
        g_area[b][pos0] = (box[0].z - box[0].x) * (box[0].w - box[0].y);
    }
    if (eb < PRE) {
        g_boxes[b][pos1] = box[1];
        g_area[b][pos1] = (box[1].z - box[1].x) * (box[1].w - box[1].y);
    }
    if (tid == 0) g_nvalid[b] = nv;
}

// Transformed IoU test: iou > 0.7 <=> inter > (7/17)*(areai+areaj) in reals.
// Per-thread kA = c*areai hoisted; per-column kB = c*areaj staged in shared.
// Inner test is FADD+FSETP per band. Band +-1e-5 relative absorbs all extra
// roundings; ambiguous pairs fall back to the exact reference formula.
// (1e-8 union clamp provably never binds for valid x valid pairs; pairs
// involving invalid boxes are don't-care: scan never reads/uses them.)
#define C_HI 0.41177000588f   /* (7/17)*(1+1e-5) */
#define C_LO 0.41176177060f   /* (7/17)*(1-1e-5) */

__global__ void __launch_bounds__(64) k_mask() {
    int b = blockIdx.y;
    int t = threadIdx.x;
    int lin = blockIdx.x, rblk = 0;
    while (lin >= 32 - rblk) { lin -= 32 - rblk; rblk++; }
    int cblk = rblk + lin;
    int rb = rblk << 6, cb = cblk << 6;
    __shared__ float4 cbox[64];
    __shared__ float2 ckb[64];   // (C_HI*areaj, C_LO*areaj)
    __shared__ float carea[64];  // exact areaj for the fallback path
    {
        int j0 = cb + t;
        float4 bj = (j0 < PRE) ? g_boxes[b][j0] : make_float4(-1.f, -1.f, -1.f, -1.f);
        float aj = (j0 < PRE) ? g_area[b][j0] : 0.f;
        cbox[t] = bj;
        carea[t] = aj;
        ckb[t] = make_float2(C_HI * aj, C_LO * aj);
    }
    __syncthreads();
    int i = rb + t;
    if (i >= PRE) return;
    float4 bi = g_boxes[b][i];
    float areai = g_area[b][i];
    float kAhi = C_HI * areai;
    float kAlo = C_LO * areai;
    ull bits = 0ULL, amb = 0ULL;
    int c0 = (cblk == rblk) ? (t + 1) : 0;
#pragma unroll 8
    for (int c = c0; c < 64; c++) {
        float4 bj = cbox[c];
        float2 kb = ckb[c];
        float w = fmaxf(fminf(bi.z, bj.z) - fmaxf(bi.x, bj.x), 0.f);
        float h = fmaxf(fminf(bi.w, bj.w) - fmaxf(bi.y, bj.y), 0.f);
        float inter = w * h;
        bool s1 = inter > (kAhi + kb.x);
        bool a1 = (!s1) && (inter >= (kAlo + kb.y));
        bits |= ((ull)s1) << c;
        amb |= ((ull)a1) << c;
    }
    while (amb) {  // rare: exact reference-formula decision
        int c = __ffsll(amb) - 1;
        amb &= amb - 1;
        float4 bj = cbox[c];
        float w = fmaxf(fminf(bi.z, bj.z) - fmaxf(bi.x, bj.x), 0.f);
        float h = fmaxf(fminf(bi.w, bj.w) - fmaxf(bi.y, bj.y), 0.f);
        float inter = w * h;
        float um = fmaxf((areai + carea[c]) - inter, 1e-8f);
        if (__fdiv_rn(inter, um) > 0.7f) bits |= 1ULL << c;
    }
    g_mask[b][i][cblk] = bits;
}

__global__ void __launch_bounds__(256) k_scan(float4* __restrict__ out) {
    __shared__ ull ring[4][16][32];
    __shared__ int sel[POST];
    __shared__ int skc;
    int b = blockIdx.x;
    int tid = threadIdx.x;
    if (tid < 32) {
        int lane = tid;
        int nv = g_nvalid[b];
        int lo = lane * 64;
        ull rem;
        if (nv <= lo) rem = ~0ULL;
        else if (nv >= lo + 64) rem = 0ULL;
        else rem = (~0ULL) << (nv - lo);
        for (int nb = 0; nb < 3; nb++) {
#pragma unroll
            for (int q = 0; q < 16; q++)
                CP8(smaddr(&ring[nb][q][lane]), &g_mask[b][nb * 16 + q][lane]);
            CPCOMMIT();
        }
        int limit = (PRE < nv) ? PRE : nv;
        int kc = 0, w = 0;
        ull r = 0ULL;
        for (int bt = 0; bt < PRE / 16; bt++) {
            CPWAIT2();
            __syncwarp();
            int base = bt * 16;
            if (base >= limit) break;
            if ((base & 63) == 0) {
                w = base >> 6;
                r = __shfl_sync(0xffffffffu, rem, w);
            }
            ull m[16];
            unsigned keptm = 0;
            if (lane == 0) {
#pragma unroll
                for (int q = 0; q < 16; q++) m[q] = ring[bt & 3][q][w];
                int off = base & 63;
#pragma unroll
                for (int q = 0; q < 16; q++) {
                    int row = base + q;
                    bool keep = (row < limit) && !((r >> (off + q)) & 1ULL);
                    if (keep) {
                        if (kc < POST) sel[kc] = row;
                        kc++;
                        keptm |= 1u << q;
                        r |= m[q];
                    }
                }
            }
            keptm = __shfl_sync(0xffffffffu, keptm, 0);
            ull acc = 0ULL;
#pragma unroll
            for (int q = 0; q < 16; q++)
                if ((keptm >> q) & 1u) acc |= ring[bt & 3][q][lane];
            if (lane >= w) rem |= acc;
            kc = __shfl_sync(0xffffffffu, kc, 0);
            if (kc >= POST) break;
            int nb = bt + 3;
            if (nb < PRE / 16) {
#pragma unroll
                for (int q = 0; q < 16; q++)
                    CP8(smaddr(&ring[nb & 3][q][lane]), &g_mask[b][nb * 16 + q][lane]);
            }
            CPCOMMIT();
        }
        CPWAITALL();
        if (lane == 0) skc = (kc < POST) ? kc : POST;
    }
    __syncthreads();
    int kc = skc;
    for (int k = tid; k < POST; k += blockDim.x) {
        float4 v = make_float4(0.f, 0.f, 0.f, 0.f);
        if (k < kc) v = g_boxes[b][sel[k]];
        out[(size_t)b * POST + k] = v;
    }
}

extern "C" void kernel_launch(void* const* d_in, const int* in_sizes, int n_in,
                              void* d_out, int out_size) {
    const float* cls = (const float*)d_in[0];
    const float* reg = (const float*)d_in[1];
    const float* anchors = (const float*)d_in[2];
    float4* out = (float4*)d_out;

    k_hist<<<dim3(NBLK, BB), 256>>>(cls);
    k_cut<<<BB, 256>>>(cls);
    k_compact<<<dim3(NBLK, BB), 256>>>(cls);
    k_sortdecode<<<BB, 1024>>>(reg, anchors);
    k_mask<<<dim3(528, BB), 64>>>();
    k_scan<<<BB, 256>>>(out);
}

// round 11
// speedup vs baseline: 1.2022x; 1.0657x over previous
#include <cuda_runtime.h>
#include <math.h>

#define BB 16
#define NN 300000
#define NV 75000
#define NBLK 37
#define PRE 2000
#define POST 1000
#define CANDMAX 4096
#define MASKW 32
#define STAGE 1024

typedef unsigned long long ull;

__device__ unsigned g_hist[BB][2048];   // zeroed by k_scan for next replay
__device__ int g_cut[BB];
__device__ unsigned g_ccount[BB];       // zeroed by k_scan for next replay
__device__ ull g_cand[BB][CANDMAX];
__device__ float4 g_boxes[BB][PRE];
__device__ float g_area[BB][PRE];
__device__ int g_nvalid[BB];
__device__ ull g_mask[BB][PRE][MASKW];

__device__ __forceinline__ unsigned keyf(float f) {
    unsigned u = __float_as_uint(f);
    return u ^ ((u >> 31) ? 0xFFFFFFFFu : 0x80000000u);
}

__device__ __forceinline__ unsigned smaddr(const void* p) {
    return (unsigned)__cvta_generic_to_shared(p);
}
#define CP8(dst, src) asm volatile("cp.async.ca.shared.global [%0], [%1], 8;" :: "r"(dst), "l"(src))
#define CPCOMMIT() asm volatile("cp.async.commit_group;")
#define CPWAIT2() asm volatile("cp.async.wait_group 2;")
#define CPWAITALL() asm volatile("cp.async.wait_all;")

// Histogram of non-negative scores, reduced straight into g_hist via global
// atomics (<=37 adds per bin). g_hist arrives zeroed (module init / k_scan).
__global__ void __launch_bounds__(256) k_hist(const float* __restrict__ cls) {
    __shared__ unsigned sh[2048];
    int b = blockIdx.y;
    int t = threadIdx.x;
    for (int i = t; i < 2048; i += 256) sh[i] = 0u;
    __syncthreads();
    const float4* __restrict__ p = (const float4*)(cls + (size_t)b * NN);
    int base = blockIdx.x * 2048;
    if (base + 2048 <= NV) {
        float4 v[8];
#pragma unroll
        for (int k = 0; k < 8; k++) v[k] = p[base + t + 256 * k];
#pragma unroll
        for (int k = 0; k < 8; k++) {
            unsigned kk[4] = {keyf(v[k].x), keyf(v[k].y), keyf(v[k].z), keyf(v[k].w)};
#pragma unroll
            for (int q = 0; q < 4; q++)
                if (kk[q] >= 0x80000000u) atomicAdd(&sh[(kk[q] >> 20) - 2048], 1u);
        }
    } else {
        for (int k = 0; k < 8; k++) {
            int id = base + t + 256 * k;
            if (id < NV) {
                float4 v = p[id];
                unsigned kk[4] = {keyf(v.x), keyf(v.y), keyf(v.z), keyf(v.w)};
#pragma unroll
                for (int q = 0; q < 4; q++)
                    if (kk[q] >= 0x80000000u) atomicAdd(&sh[(kk[q] >> 20) - 2048], 1u);
            }
        }
    }
    __syncthreads();
    for (int i = t; i < 2048; i += 256) {
        unsigned c = sh[i];
        if (c) atomicAdd(&g_hist[b][i], c);
    }
}

// Compact. Prologue: each block computes the radix cut itself from g_hist via
// a parallel suffix scan (replaces the k_cut launch). Cold fallback (cut not
// in the non-negative half) rebuilds the full histogram — never taken here.
__global__ void __launch_bounds__(256) k_compact(const float* __restrict__ cls) {
    __shared__ ull stage[STAGE];
    __shared__ unsigned hist4[4096];   // cold path only
    __shared__ unsigned wsum[8];
    __shared__ unsigned wsuf[9];
    __shared__ int s_cut;
    __shared__ unsigned s_cnt, s_base;
    int b = blockIdx.y;
    int t = threadIdx.x;
    int lane = t & 31, wid = t >> 5;
    const float4* __restrict__ p = (const float4*)(cls + (size_t)b * NN);
    // ---- cut computation ----
    unsigned hv[8];
    unsigned s = 0;
#pragma unroll
    for (int q = 0; q < 8; q++) { hv[q] = g_hist[b][t * 8 + q]; s += hv[q]; }
    // within-warp inclusive suffix sum of s
    unsigned v = s;
#pragma unroll
    for (int o = 1; o < 32; o <<= 1) {
        unsigned t2 = __shfl_down_sync(0xffffffffu, v, o);
        if (lane + o < 32) v += t2;
    }
    if (lane == 0) wsum[wid] = v;
    __syncthreads();
    if (t < 8) {
        unsigned x = 0;
        for (int j = t; j < 8; j++) x += wsum[j];
        wsuf[t] = x;
    }
    if (t == 8) wsuf[8] = 0u;
    __syncthreads();
    unsigned suf_t = v + wsuf[wid + 1];  // sum of bins in chunks t..255
    bool found = (wsuf[0] >= PRE);
    if (found && suf_t >= PRE && (suf_t - s) < PRE) {
        // crossing chunk: scan my 8 bins from the top
        unsigned acc = suf_t - s;
        int cut = 2048 + t * 8;
#pragma unroll
        for (int i = 7; i >= 0; i--) {
            if (acc + hv[i] >= PRE) { cut = 2048 + t * 8 + i; break; }
            acc += hv[i];
        }
        s_cut = cut;
    }
    __syncthreads();
    if (!found) {  // cold: full-range histogram by this block (correct, slow)
        for (int i = t; i < 4096; i += 256) hist4[i] = 0u;
        __syncthreads();
        for (int id = t; id < NV; id += 256) {
            float4 vv = p[id];
            atomicAdd(&hist4[keyf(vv.x) >> 20], 1u);
            atomicAdd(&hist4[keyf(vv.y) >> 20], 1u);
            atomicAdd(&hist4[keyf(vv.z) >> 20], 1u);
            atomicAdd(&hist4[keyf(vv.w) >> 20], 1u);
        }
        __syncthreads();
        if (t == 0) {
            unsigned acc = 0;
            int cut = 0;
            for (int c = 4095; c >= 0; c--) {
                unsigned h = hist4[c];
                if (acc + h >= PRE) { cut = c; break; }
                acc += h;
            }
            s_cut = cut;
        }
        __syncthreads();
    }
    int cut = s_cut;
    if (t == 0 && blockIdx.x == 0) g_cut[b] = cut;   // for k_sortdecode
    if (t == 0) s_cnt = 0u;
    __syncthreads();
    // ---- filter + block-aggregated emission ----
    int base = blockIdx.x * 2048;
    if (base + 2048 <= NV) {
        float4 vv[8];
#pragma unroll
        for (int k = 0; k < 8; k++) vv[k] = p[base + t + 256 * k];
#pragma unroll
        for (int k = 0; k < 8; k++) {
            int id = base + t + 256 * k;
            unsigned kk[4] = {keyf(vv[k].x), keyf(vv[k].y), keyf(vv[k].z), keyf(vv[k].w)};
#pragma unroll
            for (int q = 0; q < 4; q++) {
                if ((int)(kk[q] >> 20) >= cut) {
                    unsigned r = atomicAdd(&s_cnt, 1u);
                    if (r < STAGE)
                        stage[r] = ((ull)kk[q] << 32) | (unsigned)(~(4 * id + q));
                }
            }
        }
    } else {
        for (int k = 0; k < 8; k++) {
            int id = base + t + 256 * k;
            if (id < NV) {
                float4 vv = p[id];
                unsigned kk[4] = {keyf(vv.x), keyf(vv.y), keyf(vv.z), keyf(vv.w)};
#pragma unroll
                for (int q = 0; q < 4; q++) {
                    if ((int)(kk[q] >> 20) >= cut) {
                        unsigned r = atomicAdd(&s_cnt, 1u);
                        if (r < STAGE)
                            stage[r] = ((ull)kk[q] << 32) | (unsigned)(~(4 * id + q));
                    }
                }
            }
        }
    }
    __syncthreads();
    if (t == 0) {
        unsigned c = s_cnt < STAGE ? s_cnt : STAGE;
        s_base = atomicAdd(&g_ccount[b], c);
    }
    __syncthreads();
    unsigned c = s_cnt < STAGE ? s_cnt : STAGE;
    for (unsigned r = t; r < c; r += 256) {
        unsigned pos = s_base + r;
        if (pos < CANDMAX) g_cand[b][pos] = stage[r];
    }
}

#define CSW(a, c, d) { if ((d) ? ((a) < (c)) : ((a) > (c))) { ull _t = (a); (a) = (c); (c) = _t; } }
#define KM(e, o) ((kmax) ? ((e) > (o) ? (e) : (o)) : ((e) < (o) ? (e) : (o)))
#define SHFLP() { \
    int m = j >> 2; \
    bool kmax = (desc != ((tid & m) != 0)); \
    ull o0 = __shfl_xor_sync(0xffffffffu, e0, m); \
    ull o1 = __shfl_xor_sync(0xffffffffu, e1, m); \
    ull o2 = __shfl_xor_sync(0xffffffffu, e2, m); \
    ull o3 = __shfl_xor_sync(0xffffffffu, e3, m); \
    e0 = KM(e0, o0); e1 = KM(e1, o1); e2 = KM(e2, o2); e3 = KM(e3, o3); }

__global__ void __launch_bounds__(1024)
k_sortdecode(const float* __restrict__ reg, const float* __restrict__ anchors) {
    __shared__ ull sk[CANDMAX];
    __shared__ int swsum[32];
    __shared__ unsigned fh[256];
    __shared__ int s_fcut, s_kept;
    int b = blockIdx.x;
    int tid = threadIdx.x;
    int lane = tid & 31, wid = tid >> 5;
    unsigned n = g_ccount[b];
    if (n > CANDMAX) n = CANDMAX;
    int cut = g_cut[b];
    int b4 = 4 * tid;
    ull c0 = (b4 + 0 < (int)n) ? g_cand[b][b4 + 0] : 0ULL;
    ull c1 = (b4 + 1 < (int)n) ? g_cand[b][b4 + 1] : 0ULL;
    ull c2 = (b4 + 2 < (int)n) ? g_cand[b][b4 + 2] : 0ULL;
    ull c3 = (b4 + 3 < (int)n) ? g_cand[b][b4 + 3] : 0ULL;
    if (tid < 256) fh[tid] = 0u;
    __syncthreads();
#define FH(ci, off) { if (b4 + off < (int)n) { unsigned key = (unsigned)((ci) >> 32); \
        if ((int)(key >> 20) == cut) atomicAdd(&fh[(key >> 12) & 0xFF], 1u); } }
    FH(c0, 0) FH(c1, 1) FH(c2, 2) FH(c3, 3)
#undef FH
    __syncthreads();
    if (tid == 0) {
        unsigned tie = 0;
        for (int f = 0; f < 256; f++) tie += fh[f];
        int nab = (int)n - (int)tie;
        int acc = 0, fcut = 0, kept = (int)n;
        for (int f = 255; f >= 0; f--) {
            if (nab + acc + (int)fh[f] >= PRE) { fcut = f; kept = nab + acc + (int)fh[f]; break; }
            acc += (int)fh[f];
        }
        s_fcut = fcut;
        s_kept = kept;
    }
    __syncthreads();
    int kept = s_kept, fcut = s_fcut;
    ull e0 = 0, e1 = 0, e2 = 0, e3 = 0;
    if (kept <= 2048) {
        int p0 = 0, p1 = 0, p2 = 0, p3 = 0;
#define PRED(ci, pi, off) { if (b4 + off < (int)n) { unsigned key = (unsigned)((ci) >> 32); \
        pi = ((int)(key >> 20) > cut) || ((int)((key >> 12) & 0xFF) >= fcut); } }
        PRED(c0, p0, 0) PRED(c1, p1, 1) PRED(c2, p2, 2) PRED(c3, p3, 3)
#undef PRED
        int cnt = p0 + p1 + p2 + p3;
        int v = cnt;
        for (int o = 1; o < 32; o <<= 1) {
            int t2 = __shfl_up_sync(0xffffffffu, v, o);
            if (lane >= o) v += t2;
        }
        if (lane == 31) swsum[wid] = v;
        __syncthreads();
        if (wid == 0) {
            int x = swsum[lane];
            for (int o = 1; o < 32; o <<= 1) {
                int t2 = __shfl_up_sync(0xffffffffu, x, o);
                if (lane >= o) x += t2;
            }
            swsum[lane] = x;
        }
        __syncthreads();
        int excl = v - cnt + (wid ? swsum[wid - 1] : 0);
        sk[tid] = 0ULL;
        sk[tid + 1024] = 0ULL;
        __syncthreads();
        int pos = excl;
        if (p0) sk[pos++] = c0;
        if (p1) sk[pos++] = c1;
        if (p2) sk[pos++] = c2;
        if (p3) sk[pos++] = c3;
        __syncthreads();
        bool act = (tid < 512);
        if (act) {
            e0 = sk[b4]; e1 = sk[b4 + 1]; e2 = sk[b4 + 2]; e3 = sk[b4 + 3];
            CSW(e0, e1, true);
            CSW(e2, e3, false);
        }
        for (int k = 4; k <= 2048; k <<= 1) {
            bool desc = ((b4 & k) == 0);
            for (int j = k >> 1; j >= 128; j >>= 1) {
                if (act) { sk[b4] = e0; sk[b4 + 1] = e1; sk[b4 + 2] = e2; sk[b4 + 3] = e3; }
                __syncthreads();
                if (act) {
                    int m = j >> 2;
                    int pt = 4 * (tid ^ m);
                    bool kmax = (desc != ((tid & m) != 0));
                    ull o0 = sk[pt], o1 = sk[pt + 1], o2 = sk[pt + 2], o3 = sk[pt + 3];
                    e0 = KM(e0, o0); e1 = KM(e1, o1); e2 = KM(e2, o2); e3 = KM(e3, o3);
                }
                __syncthreads();
            }
            if (act) {
                int jstart = (k >> 1) < 64 ? (k >> 1) : 64;
                for (int j = jstart; j >= 4; j >>= 1) SHFLP()
                CSW(e0, e2, desc); CSW(e1, e3, desc);
                CSW(e0, e1, desc); CSW(e2, e3, desc);
            }
        }
        if (act) { sk[b4] = e0; sk[b4 + 1] = e1; sk[b4 + 2] = e2; sk[b4 + 3] = e3; }
        __syncthreads();
    } else {
        e0 = c0; e1 = c1; e2 = c2; e3 = c3;
        CSW(e0, e1, true);
        CSW(e2, e3, false);
        for (int k = 4; k <= CANDMAX; k <<= 1) {
            bool desc = ((b4 & k) == 0);
            for (int j = k >> 1; j >= 128; j >>= 1) {
                sk[b4] = e0; sk[b4 + 1] = e1; sk[b4 + 2] = e2; sk[b4 + 3] = e3;
                __syncthreads();
                int m = j >> 2;
                int pt = 4 * (tid ^ m);
                bool kmax = (desc != ((tid & m) != 0));
                ull o0 = sk[pt], o1 = sk[pt + 1], o2 = sk[pt + 2], o3 = sk[pt + 3];
                e0 = KM(e0, o0); e1 = KM(e1, o1); e2 = KM(e2, o2); e3 = KM(e3, o3);
                __syncthreads();
            }
            int jstart = (k >> 1) < 64 ? (k >> 1) : 64;
            for (int j = jstart; j >= 4; j >>= 1) SHFLP()
            CSW(e0, e2, desc); CSW(e1, e3, desc);
            CSW(e0, e1, desc); CSW(e2, e3, desc);
        }
        sk[b4] = e0; sk[b4 + 1] = e1; sk[b4 + 2] = e2; sk[b4 + 3] = e3;
        __syncthreads();
    }
    float4 box[2];
    int val[2];
#pragma unroll
    for (int q = 0; q < 2; q++) {
        int e = 2 * tid + q;
        val[q] = 0;
        box[q] = make_float4(0.f, 0.f, 0.f, 0.f);
        if (e < PRE) {
            unsigned idx = ~(unsigned)(sk[e] & 0xFFFFFFFFULL);
            const float* a = anchors + ((size_t)b * NN + idx) * 4;
            const float* r = reg + ((size_t)b * NN + idx) * 4;
            float a0 = a[0], a1 = a[1], a2 = a[2], a3 = a[3];
            float dx = r[0], dy = r[1], dw = r[2], dh = r[3];
            float aw = a2 - a0, ah = a3 - a1;
            float acx = a0 + 0.5f * aw, acy = a1 + 0.5f * ah;
            float pcx = dx * aw + acx, pcy = dy * ah + acy;
            float pw = expf(dw) * aw, ph = expf(dh) * ah;
            float x1 = pcx - 0.5f * pw, y1 = pcy - 0.5f * ph;
            float x2 = pcx + 0.5f * pw, y2 = pcy + 0.5f * ph;
            x1 = fminf(fmaxf(x1, 0.f), 1333.f);
            y1 = fminf(fmaxf(y1, 0.f), 800.f);
            x2 = fminf(fmaxf(x2, 0.f), 1333.f);
            y2 = fminf(fmaxf(y2, 0.f), 800.f);
            float w = x2 - x1, h = y2 - y1;
            val[q] = (w >= 0.001f && h >= 0.001f) ? 1 : 0;
            box[q] = make_float4(x1, y1, x2, y2);
        }
    }
    int pairsum = val[0] + val[1];
    int v = pairsum;
    for (int o = 1; o < 32; o <<= 1) {
        int t2 = __shfl_up_sync(0xffffffffu, v, o);
        if (lane >= o) v += t2;
    }
    if (lane == 31) swsum[wid] = v;
    __syncthreads();
    if (wid == 0) {
        int x = swsum[lane];
        for (int o = 1; o < 32; o <<= 1) {
            int t2 = __shfl_up_sync(0xffffffffu, x, o);
            if (lane >= o) x += t2;
        }
        swsum[lane] = x;
    }
    __syncthreads();
    int incl = v + (wid ? swsum[wid - 1] : 0);
    int excl = incl - pairsum;
    int nv = swsum[31];
    int ea = 2 * tid, eb = 2 * tid + 1;
    int rank0 = excl;
    int rank1 = excl + val[0];
    int pos0 = val[0] ? rank0 : nv + (ea - rank0);
    int pos1 = val[1] ? rank1 : nv + (eb - rank1);
    if (ea < PRE) {
        g_boxes[b][pos0] = box[0];
        g_area[b][pos0] = (box[0].z - box[0].x) * (box[0].w - box[0].y);
    }
    if (eb < PRE) {
        g_boxes[b][pos1] = box[1];
        g_area[b][pos1] = (box[1].z - box[1].x) * (box[1].w - box[1].y);
    }
    if (tid == 0) g_nvalid[b] = nv;
}

#define C_HI 0.41177000588f   /* (7/17)*(1+1e-5) */
#define C_LO 0.41176177060f   /* (7/17)*(1-1e-5) */

__global__ void __launch_bounds__(64) k_mask() {
    int b = blockIdx.y;
    int t = threadIdx.x;
    int lin = blockIdx.x, rblk = 0;
    while (lin >= 32 - rblk) { lin -= 32 - rblk; rblk++; }
    int cblk = rblk + lin;
    int rb = rblk << 6, cb = cblk << 6;
    __shared__ float4 cbox[64];
    __shared__ float2 ckb[64];
    __shared__ float carea[64];
    {
        int j0 = cb + t;
        float4 bj = (j0 < PRE) ? g_boxes[b][j0] : make_float4(-1.f, -1.f, -1.f, -1.f);
        float aj = (j0 < PRE) ? g_area[b][j0] : 0.f;
        cbox[t] = bj;
        carea[t] = aj;
        ckb[t] = make_float2(C_HI * aj, C_LO * aj);
    }
    __syncthreads();
    int i = rb + t;
    if (i >= PRE) return;
    float4 bi = g_boxes[b][i];
    float areai = g_area[b][i];
    float kAhi = C_HI * areai;
    float kAlo = C_LO * areai;
    ull bits = 0ULL, amb = 0ULL;
    int c0 = (cblk == rblk) ? (t + 1) : 0;
#pragma unroll 8
    for (int c = c0; c < 64; c++) {
        float4 bj = cbox[c];
        float2 kb = ckb[c];
        float w = fmaxf(fminf(bi.z, bj.z) - fmaxf(bi.x, bj.x), 0.f);
        float h = fmaxf(fminf(bi.w, bj.w) - fmaxf(bi.y, bj.y), 0.f);
        float inter = w * h;
        bool s1 = inter > (kAhi + kb.x);
        bool a1 = (!s1) && (inter >= (kAlo + kb.y));
        bits |= ((ull)s1) << c;
        amb |= ((ull)a1) << c;
    }
    while (amb) {
        int c = __ffsll(amb) - 1;
        amb &= amb - 1;
        float4 bj = cbox[c];
        float w = fmaxf(fminf(bi.z, bj.z) - fmaxf(bi.x, bj.x), 0.f);
        float h = fmaxf(fminf(bi.w, bj.w) - fmaxf(bi.y, bj.y), 0.f);
        float inter = w * h;
        float um = fmaxf((areai + carea[c]) - inter, 1e-8f);
        if (__fdiv_rn(inter, um) > 0.7f) bits |= 1ULL << c;
    }
    g_mask[b][i][cblk] = bits;
}

__global__ void __launch_bounds__(256) k_scan(float4* __restrict__ out) {
    __shared__ ull ring[4][16][32];
    __shared__ int sel[POST];
    __shared__ int skc;
    int b = blockIdx.x;
    int tid = threadIdx.x;
    if (tid < 32) {
        int lane = tid;
        int nv = g_nvalid[b];
        int lo = lane * 64;
        ull rem;
        if (nv <= lo) rem = ~0ULL;
        else if (nv >= lo + 64) rem = 0ULL;
        else rem = (~0ULL) << (nv - lo);
        for (int nb = 0; nb < 3; nb++) {
#pragma unroll
            for (int q = 0; q < 16; q++)
                CP8(smaddr(&ring[nb][q][lane]), &g_mask[b][nb * 16 + q][lane]);
            CPCOMMIT();
        }
        int limit = (PRE < nv) ? PRE : nv;
        int kc = 0, w = 0;
        ull r = 0ULL;
        for (int bt = 0; bt < PRE / 16; bt++) {
            CPWAIT2();
            __syncwarp();
            int base = bt * 16;
            if (base >= limit) break;
            if ((base & 63) == 0) {
                w = base >> 6;
                r = __shfl_sync(0xffffffffu, rem, w);
            }
            ull m[16];
            unsigned keptm = 0;
            if (lane == 0) {
#pragma unroll
                for (int q = 0; q < 16; q++) m[q] = ring[bt & 3][q][w];
                int off = base & 63;
#pragma unroll
                for (int q = 0; q < 16; q++) {
                    int row = base + q;
                    bool keep = (row < limit) && !((r >> (off + q)) & 1ULL);
                    if (keep) {
                        if (kc < POST) sel[kc] = row;
                        kc++;
                        keptm |= 1u << q;
                        r |= m[q];
                    }
                }
            }
            keptm = __shfl_sync(0xffffffffu, keptm, 0);
            ull acc = 0ULL;
#pragma unroll
            for (int q = 0; q < 16; q++)
                if ((keptm >> q) & 1u) acc |= ring[bt & 3][q][lane];
            if (lane >= w) rem |= acc;
            kc = __shfl_sync(0xffffffffu, kc, 0);
            if (kc >= POST) break;
            int nb = bt + 3;
            if (nb < PRE / 16) {
#pragma unroll
                for (int q = 0; q < 16; q++)
                    CP8(smaddr(&ring[nb & 3][q][lane]), &g_mask[b][nb * 16 + q][lane]);
            }
            CPCOMMIT();
        }
        CPWAITALL();
        if (lane == 0) skc = (kc < POST) ? kc : POST;
    }
    __syncthreads();
    int kc = skc;
    for (int k = tid; k < POST; k += blockDim.x) {
        float4 v = make_float4(0.f, 0.f, 0.f, 0.f);
        if (k < kc) v = g_boxes[b][sel[k]];
        out[(size_t)b * POST + k] = v;
    }
    // restore state for next graph replay (independent of output writes)
    for (int k = tid; k < 2048; k += blockDim.x) g_hist[b][k] = 0u;
    if (tid == 0) g_ccount[b] = 0u;
}

extern "C" void kernel_launch(void* const* d_in, const int* in_sizes, int n_in,
                              void* d_out, int out_size) {
    const float* cls = (const float*)d_in[0];
    const float* reg = (const float*)d_in[1];
    const float* anchors = (const float*)d_in[2];
    float4* out = (float4*)d_out;

    k_hist<<<dim3(NBLK, BB), 256>>>(cls);
    k_compact<<<dim3(NBLK, BB), 256>>>(cls);
    k_sortdecode<<<BB, 1024>>>(reg, anchors);
    k_mask<<<dim3(528, BB), 64>>>();
    k_scan<<<BB, 256>>>(out);
}

// round 12
// speedup vs baseline: 1.2466x; 1.0369x over previous
#include <cuda_runtime.h>
#include <math.h>

#define BB 16
#define NN 300000
#define NV 75000
#define NBLK 37
#define PRE 2000
#define POST 1000
#define CANDMAX 4096
#define MASKW 32
#define STAGE 1024

typedef unsigned long long ull;

__device__ unsigned g_hist[BB][2048];   // zeroed by k_scan for next replay
__device__ int g_cut[BB];
__device__ unsigned g_ccount[BB];       // zeroed by k_scan for next replay
__device__ ull g_cand[BB][CANDMAX];
__device__ float4 g_boxes[BB][PRE];
__device__ float g_area[BB][PRE];
__device__ int g_nvalid[BB];
__device__ ull g_mask[BB][PRE][MASKW];

__device__ __forceinline__ unsigned keyf(float f) {
    unsigned u = __float_as_uint(f);
    return u ^ ((u >> 31) ? 0xFFFFFFFFu : 0x80000000u);
}

__device__ __forceinline__ unsigned smaddr(const void* p) {
    return (unsigned)__cvta_generic_to_shared(p);
}
#define CP8(dst, src) asm volatile("cp.async.ca.shared.global [%0], [%1], 8;" :: "r"(dst), "l"(src))
#define CPCOMMIT() asm volatile("cp.async.commit_group;")
#define CPWAIT2() asm volatile("cp.async.wait_group 2;")
#define CPWAITALL() asm volatile("cp.async.wait_all;")

__global__ void __launch_bounds__(256) k_hist(const float* __restrict__ cls) {
    __shared__ unsigned sh[2048];
    int b = blockIdx.y;
    int t = threadIdx.x;
    for (int i = t; i < 2048; i += 256) sh[i] = 0u;
    __syncthreads();
    const float4* __restrict__ p = (const float4*)(cls + (size_t)b * NN);
    int base = blockIdx.x * 2048;
    if (base + 2048 <= NV) {
        float4 v[8];
#pragma unroll
        for (int k = 0; k < 8; k++) v[k] = p[base + t + 256 * k];
#pragma unroll
        for (int k = 0; k < 8; k++) {
            unsigned kk[4] = {keyf(v[k].x), keyf(v[k].y), keyf(v[k].z), keyf(v[k].w)};
#pragma unroll
            for (int q = 0; q < 4; q++)
                if (kk[q] >= 0x80000000u) atomicAdd(&sh[(kk[q] >> 20) - 2048], 1u);
        }
    } else {
        for (int k = 0; k < 8; k++) {
            int id = base + t + 256 * k;
            if (id < NV) {
                float4 v = p[id];
                unsigned kk[4] = {keyf(v.x), keyf(v.y), keyf(v.z), keyf(v.w)};
#pragma unroll
                for (int q = 0; q < 4; q++)
                    if (kk[q] >= 0x80000000u) atomicAdd(&sh[(kk[q] >> 20) - 2048], 1u);
            }
        }
    }
    __syncthreads();
    for (int i = t; i < 2048; i += 256) {
        unsigned c = sh[i];
        if (c) atomicAdd(&g_hist[b][i], c);
    }
}

__global__ void __launch_bounds__(256) k_compact(const float* __restrict__ cls) {
    __shared__ ull stage[STAGE];
    __shared__ unsigned hist4[4096];   // cold path only
    __shared__ unsigned wsum[8];
    __shared__ unsigned wsuf[9];
    __shared__ int s_cut;
    __shared__ unsigned s_cnt, s_base;
    int b = blockIdx.y;
    int t = threadIdx.x;
    int lane = t & 31, wid = t >> 5;
    const float4* __restrict__ p = (const float4*)(cls + (size_t)b * NN);
    // ---- cut computation (parallel suffix scan over g_hist) ----
    unsigned hv[8];
    unsigned s = 0;
#pragma unroll
    for (int q = 0; q < 8; q++) { hv[q] = g_hist[b][t * 8 + q]; s += hv[q]; }
    unsigned v = s;
#pragma unroll
    for (int o = 1; o < 32; o <<= 1) {
        unsigned t2 = __shfl_down_sync(0xffffffffu, v, o);
        if (lane + o < 32) v += t2;
    }
    if (lane == 0) wsum[wid] = v;
    __syncthreads();
    if (t < 8) {
        unsigned x = 0;
        for (int j = t; j < 8; j++) x += wsum[j];
        wsuf[t] = x;
    }
    if (t == 8) wsuf[8] = 0u;
    __syncthreads();
    unsigned suf_t = v + wsuf[wid + 1];
    bool found = (wsuf[0] >= PRE);
    if (found && suf_t >= PRE && (suf_t - s) < PRE) {
        unsigned acc = suf_t - s;
        int cut = 2048 + t * 8;
#pragma unroll
        for (int i = 7; i >= 0; i--) {
            if (acc + hv[i] >= PRE) { cut = 2048 + t * 8 + i; break; }
            acc += hv[i];
        }
        s_cut = cut;
    }
    __syncthreads();
    if (!found) {  // cold fallback: full-range histogram by this block
        for (int i = t; i < 4096; i += 256) hist4[i] = 0u;
        __syncthreads();
        for (int id = t; id < NV; id += 256) {
            float4 vv = p[id];
            atomicAdd(&hist4[keyf(vv.x) >> 20], 1u);
            atomicAdd(&hist4[keyf(vv.y) >> 20], 1u);
            atomicAdd(&hist4[keyf(vv.z) >> 20], 1u);
            atomicAdd(&hist4[keyf(vv.w) >> 20], 1u);
        }
        __syncthreads();
        if (t == 0) {
            unsigned acc = 0;
            int cut = 0;
            for (int c = 4095; c >= 0; c--) {
                unsigned h = hist4[c];
                if (acc + h >= PRE) { cut = c; break; }
                acc += h;
            }
            s_cut = cut;
        }
        __syncthreads();
    }
    int cut = s_cut;
    if (t == 0 && blockIdx.x == 0) g_cut[b] = cut;
    if (t == 0) s_cnt = 0u;
    __syncthreads();
    // ---- filter + block-aggregated emission ----
    int base = blockIdx.x * 2048;
    if (base + 2048 <= NV) {
        float4 vv[8];
#pragma unroll
        for (int k = 0; k < 8; k++) vv[k] = p[base + t + 256 * k];
#pragma unroll
        for (int k = 0; k < 8; k++) {
            int id = base + t + 256 * k;
            unsigned kk[4] = {keyf(vv[k].x), keyf(vv[k].y), keyf(vv[k].z), keyf(vv[k].w)};
#pragma unroll
            for (int q = 0; q < 4; q++) {
                if ((int)(kk[q] >> 20) >= cut) {
                    unsigned r = atomicAdd(&s_cnt, 1u);
                    if (r < STAGE)
                        stage[r] = ((ull)kk[q] << 32) | (unsigned)(~(4 * id + q));
                }
            }
        }
    } else {
        for (int k = 0; k < 8; k++) {
            int id = base + t + 256 * k;
            if (id < NV) {
                float4 vv = p[id];
                unsigned kk[4] = {keyf(vv.x), keyf(vv.y), keyf(vv.z), keyf(vv.w)};
#pragma unroll
                for (int q = 0; q < 4; q++) {
                    if ((int)(kk[q] >> 20) >= cut) {
                        unsigned r = atomicAdd(&s_cnt, 1u);
                        if (r < STAGE)
                            stage[r] = ((ull)kk[q] << 32) | (unsigned)(~(4 * id + q));
                    }
                }
            }
        }
    }
    __syncthreads();
    if (t == 0) {
        unsigned c = s_cnt < STAGE ? s_cnt : STAGE;
        s_base = atomicAdd(&g_ccount[b], c);
    }
    __syncthreads();
    unsigned c = s_cnt < STAGE ? s_cnt : STAGE;
    for (unsigned r = t; r < c; r += 256) {
        unsigned pos = s_base + r;
        if (pos < CANDMAX) g_cand[b][pos] = stage[r];
    }
}

#define CSW(a, c, d) { if ((d) ? ((a) < (c)) : ((a) > (c))) { ull _t = (a); (a) = (c); (c) = _t; } }
#define KM(e, o) ((kmax) ? ((e) > (o) ? (e) : (o)) : ((e) < (o) ? (e) : (o)))
#define SHFLP() { \
    int m = j >> 2; \
    bool kmax = (desc != ((tid & m) != 0)); \
    ull o0 = __shfl_xor_sync(0xffffffffu, e0, m); \
    ull o1 = __shfl_xor_sync(0xffffffffu, e1, m); \
    ull o2 = __shfl_xor_sync(0xffffffffu, e2, m); \
    ull o3 = __shfl_xor_sync(0xffffffffu, e3, m); \
    e0 = KM(e0, o0); e1 = KM(e1, o1); e2 = KM(e2, o2); e3 = KM(e3, o3); }

__global__ void __launch_bounds__(1024)
k_sortdecode(const float* __restrict__ reg, const float* __restrict__ anchors) {
    __shared__ ull sk[CANDMAX];
    __shared__ int swsum[32];
    __shared__ unsigned fh[256];
    __shared__ int s_fcut, s_kept;
    int b = blockIdx.x;
    int tid = threadIdx.x;
    int lane = tid & 31, wid = tid >> 5;
    unsigned n = g_ccount[b];
    if (n > CANDMAX) n = CANDMAX;
    int cut = g_cut[b];
    int b4 = 4 * tid;
    ull c0 = (b4 + 0 < (int)n) ? g_cand[b][b4 + 0] : 0ULL;
    ull c1 = (b4 + 1 < (int)n) ? g_cand[b][b4 + 1] : 0ULL;
    ull c2 = (b4 + 2 < (int)n) ? g_cand[b][b4 + 2] : 0ULL;
    ull c3 = (b4 + 3 < (int)n) ? g_cand[b][b4 + 3] : 0ULL;
    if (tid < 256) fh[tid] = 0u;
    __syncthreads();
#define FH(ci, off) { if (b4 + off < (int)n) { unsigned key = (unsigned)((ci) >> 32); \
        if ((int)(key >> 20) == cut) atomicAdd(&fh[(key >> 12) & 0xFF], 1u); } }
    FH(c0, 0) FH(c1, 1) FH(c2, 2) FH(c3, 3)
#undef FH
    __syncthreads();
    if (tid == 0) {
        unsigned tie = 0;
        for (int f = 0; f < 256; f++) tie += fh[f];
        int nab = (int)n - (int)tie;
        int acc = 0, fcut = 0, kept = (int)n;
        for (int f = 255; f >= 0; f--) {
            if (nab + acc + (int)fh[f] >= PRE) { fcut = f; kept = nab + acc + (int)fh[f]; break; }
            acc += (int)fh[f];
        }
        s_fcut = fcut;
        s_kept = kept;
    }
    __syncthreads();
    int kept = s_kept, fcut = s_fcut;
    ull e0 = 0, e1 = 0, e2 = 0, e3 = 0;
    if (kept <= 2048) {
        int p0 = 0, p1 = 0, p2 = 0, p3 = 0;
#define PRED(ci, pi, off) { if (b4 + off < (int)n) { unsigned key = (unsigned)((ci) >> 32); \
        pi = ((int)(key >> 20) > cut) || ((int)((key >> 12) & 0xFF) >= fcut); } }
        PRED(c0, p0, 0) PRED(c1, p1, 1) PRED(c2, p2, 2) PRED(c3, p3, 3)
#undef PRED
        int cnt = p0 + p1 + p2 + p3;
        int v = cnt;
        for (int o = 1; o < 32; o <<= 1) {
            int t2 = __shfl_up_sync(0xffffffffu, v, o);
            if (lane >= o) v += t2;
        }
        if (lane == 31) swsum[wid] = v;
        __syncthreads();
        if (wid == 0) {
            int x = swsum[lane];
            for (int o = 1; o < 32; o <<= 1) {
                int t2 = __shfl_up_sync(0xffffffffu, x, o);
                if (lane >= o) x += t2;
            }
            swsum[lane] = x;
        }
        __syncthreads();
        int excl = v - cnt + (wid ? swsum[wid - 1] : 0);
        sk[tid] = 0ULL;
        sk[tid + 1024] = 0ULL;
        __syncthreads();
        int pos = excl;
        if (p0) sk[pos++] = c0;
        if (p1) sk[pos++] = c1;
        if (p2) sk[pos++] = c2;
        if (p3) sk[pos++] = c3;
        __syncthreads();
        bool act = (tid < 512);
        if (act) {
            e0 = sk[b4]; e1 = sk[b4 + 1]; e2 = sk[b4 + 2]; e3 = sk[b4 + 3];
            CSW(e0, e1, true);
            CSW(e2, e3, false);
        }
        for (int k = 4; k <= 2048; k <<= 1) {
            bool desc = ((b4 & k) == 0);
            for (int j = k >> 1; j >= 128; j >>= 1) {
                if (act) { sk[b4] = e0; sk[b4 + 1] = e1; sk[b4 + 2] = e2; sk[b4 + 3] = e3; }
                __syncthreads();
                if (act) {
                    int m = j >> 2;
                    int pt = 4 * (tid ^ m);
                    bool kmax = (desc != ((tid & m) != 0));
                    ull o0 = sk[pt], o1 = sk[pt + 1], o2 = sk[pt + 2], o3 = sk[pt + 3];
                    e0 = KM(e0, o0); e1 = KM(e1, o1); e2 = KM(e2, o2); e3 = KM(e3, o3);
                }
                __syncthreads();
            }
            if (act) {
                int jstart = (k >> 1) < 64 ? (k >> 1) : 64;
                for (int j = jstart; j >= 4; j >>= 1) SHFLP()
                CSW(e0, e2, desc); CSW(e1, e3, desc);
                CSW(e0, e1, desc); CSW(e2, e3, desc);
            }
        }
        if (act) { sk[b4] = e0; sk[b4 + 1] = e1; sk[b4 + 2] = e2; sk[b4 + 3] = e3; }
        __syncthreads();
    } else {
        e0 = c0; e1 = c1; e2 = c2; e3 = c3;
        CSW(e0, e1, true);
        CSW(e2, e3, false);
        for (int k = 4; k <= CANDMAX; k <<= 1) {
            bool desc = ((b4 & k) == 0);
            for (int j = k >> 1; j >= 128; j >>= 1) {
                sk[b4] = e0; sk[b4 + 1] = e1; sk[b4 + 2] = e2; sk[b4 + 3] = e3;
                __syncthreads();
                int m = j >> 2;
                int pt = 4 * (tid ^ m);
                bool kmax = (desc != ((tid & m) != 0));
                ull o0 = sk[pt], o1 = sk[pt + 1], o2 = sk[pt + 2], o3 = sk[pt + 3];
                e0 = KM(e0, o0); e1 = KM(e1, o1); e2 = KM(e2, o2); e3 = KM(e3, o3);
                __syncthreads();
            }
            int jstart = (k >> 1) < 64 ? (k >> 1) : 64;
            for (int j = jstart; j >= 4; j >>= 1) SHFLP()
            CSW(e0, e2, desc); CSW(e1, e3, desc);
            CSW(e0, e1, desc); CSW(e2, e3, desc);
        }
        sk[b4] = e0; sk[b4 + 1] = e1; sk[b4 + 2] = e2; sk[b4 + 3] = e3;
        __syncthreads();
    }
    float4 box[2];
    int val[2];
#pragma unroll
    for (int q = 0; q < 2; q++) {
        int e = 2 * tid + q;
        val[q] = 0;
        box[q] = make_float4(0.f, 0.f, 0.f, 0.f);
        if (e < PRE) {
            unsigned idx = ~(unsigned)(sk[e] & 0xFFFFFFFFULL);
            const float* a = anchors + ((size_t)b * NN + idx) * 4;
            const float* r = reg + ((size_t)b * NN + idx) * 4;
            float a0 = a[0], a1 = a[1], a2 = a[2], a3 = a[3];
            float dx = r[0], dy = r[1], dw = r[2], dh = r[3];
            float aw = a2 - a0, ah = a3 - a1;
            float acx = a0 + 0.5f * aw, acy = a1 + 0.5f * ah;
            float pcx = dx * aw + acx, pcy = dy * ah + acy;
            float pw = expf(dw) * aw, ph = expf(dh) * ah;
            float x1 = pcx - 0.5f * pw, y1 = pcy - 0.5f * ph;
            float x2 = pcx + 0.5f * pw, y2 = pcy + 0.5f * ph;
            x1 = fminf(fmaxf(x1, 0.f), 1333.f);
            y1 = fminf(fmaxf(y1, 0.f), 800.f);
            x2 = fminf(fmaxf(x2, 0.f), 1333.f);
            y2 = fminf(fmaxf(y2, 0.f), 800.f);
            float w = x2 - x1, h = y2 - y1;
            val[q] = (w >= 0.001f && h >= 0.001f) ? 1 : 0;
            box[q] = make_float4(x1, y1, x2, y2);
        }
    }
    int pairsum = val[0] + val[1];
    int v = pairsum;
    for (int o = 1; o < 32; o <<= 1) {
        int t2 = __shfl_up_sync(0xffffffffu, v, o);
        if (lane >= o) v += t2;
    }
    if (lane == 31) swsum[wid] = v;
    __syncthreads();
    if (wid == 0) {
        int x = swsum[lane];
        for (int o = 1; o < 32; o <<= 1) {
            int t2 = __shfl_up_sync(0xffffffffu, x, o);
            if (lane >= o) x += t2;
        }
        swsum[lane] = x;
    }
    __syncthreads();
    int incl = v + (wid ? swsum[wid - 1] : 0);
    int excl = incl - pairsum;
    int nv = swsum[31];
    int ea = 2 * tid, eb = 2 * tid + 1;
    int rank0 = excl;
    int rank1 = excl + val[0];
    int pos0 = val[0] ? rank0 : nv + (ea - rank0);
    int pos1 = val[1] ? rank1 : nv + (eb - rank1);
    if (ea < PRE) {
        g_boxes[b][pos0] = box[0];
        g_area[b][pos0] = (box[0].z - box[0].x) * (box[0].w - box[0].y);
    }
    if (eb < PRE) {
        g_boxes[b][pos1] = box[1];
        g_area[b][pos1] = (box[1].z - box[1].x) * (box[1].w - box[1].y);
    }
    if (tid == 0) g_nvalid[b] = nv;
}

#define C_HI 0.41177000588f   /* (7/17)*(1+1e-5) */
#define C_LO 0.41176177060f   /* (7/17)*(1-1e-5) */

// Single-clamp IoU band test. inter' = fmaxf(w,0)*h: if w<=0 -> 0; if h<0 &
// w>0 -> negative; both cases below any positive threshold, and equal-zero
// threshold cases (padding, area 0) land in the band -> exact fallback.
__global__ void __launch_bounds__(64) k_mask() {
    int b = blockIdx.y;
    int t = threadIdx.x;
    int lin = blockIdx.x, rblk = 0;
    while (lin >= 32 - rblk) { lin -= 32 - rblk; rblk++; }
    int cblk = rblk + lin;
    int rb = rblk << 6, cb = cblk << 6;
    __shared__ float4 cbox[64];
    __shared__ float2 ckb[64];
    __shared__ float carea[64];
    {
        int j0 = cb + t;
        float4 bj = (j0 < PRE) ? g_boxes[b][j0] : make_float4(-1.f, -1.f, -1.f, -1.f);
        float aj = (j0 < PRE) ? g_area[b][j0] : 0.f;
        cbox[t] = bj;
        carea[t] = aj;
        ckb[t] = make_float2(C_HI * aj, C_LO * aj);
    }
    __syncthreads();
    int i = rb + t;
    if (i >= PRE) return;
    float4 bi = g_boxes[b][i];
    float areai = g_area[b][i];
    float kAhi = C_HI * areai;
    float kAlo = C_LO * areai;
    unsigned blo = 0u, bhi = 0u, alo = 0u, ahi = 0u;
#define IOUB(c, BL, AL, SH) { \
        float4 bj = cbox[c]; \
        float2 kb = ckb[c]; \
        float w = fmaxf(fminf(bi.z, bj.z) - fmaxf(bi.x, bj.x), 0.f); \
        float h = fminf(bi.w, bj.w) - fmaxf(bi.y, bj.y); \
        float inter = w * h; \
        bool s1 = inter > (kAhi + kb.x); \
        bool a1 = (!s1) && (inter >= (kAlo + kb.y)); \
        BL |= ((unsigned)s1) << (SH); \
        AL |= ((unsigned)a1) << (SH); }
    if (cblk == rblk) {
        for (int c = t + 1; c < 64; c++) {
            if (c < 32) { IOUB(c, blo, alo, c) }
            else { IOUB(c, bhi, ahi, c - 32) }
        }
    } else {
#pragma unroll
        for (int c = 0; c < 32; c++) { IOUB(c, blo, alo, c) }
#pragma unroll
        for (int c = 32; c < 64; c++) { IOUB(c, bhi, ahi, c - 32) }
    }
#undef IOUB
    ull bits = ((ull)bhi << 32) | blo;
    ull amb = ((ull)ahi << 32) | alo;
    while (amb) {  // rare: exact reference-formula decision
        int c = __ffsll(amb) - 1;
        amb &= amb - 1;
        float4 bj = cbox[c];
        float w = fmaxf(fminf(bi.z, bj.z) - fmaxf(bi.x, bj.x), 0.f);
        float h = fmaxf(fminf(bi.w, bj.w) - fmaxf(bi.y, bj.y), 0.f);
        float inter = w * h;
        float um = fmaxf((areai + carea[c]) - inter, 1e-8f);
        if (__fdiv_rn(inter, um) > 0.7f) bits |= 1ULL << c;
    }
    g_mask[b][i][cblk] = bits;
}

__global__ void __launch_bounds__(256) k_scan(float4* __restrict__ out) {
    __shared__ ull ring[4][16][32];
    __shared__ int sel[POST];
    __shared__ int skc;
    int b = blockIdx.x;
    int tid = threadIdx.x;
    if (tid < 32) {
        int lane = tid;
        int nv = g_nvalid[b];
        int lo = lane * 64;
        ull rem;
        if (nv <= lo) rem = ~0ULL;
        else if (nv >= lo + 64) rem = 0ULL;
        else rem = (~0ULL) << (nv - lo);
        for (int nb = 0; nb < 3; nb++) {
#pragma unroll
            for (int q = 0; q < 16; q++)
                CP8(smaddr(&ring[nb][q][lane]), &g_mask[b][nb * 16 + q][lane]);
            CPCOMMIT();
        }
        int limit = (PRE < nv) ? PRE : nv;
        int kc = 0, w = 0;
        ull r = 0ULL;
        for (int bt = 0; bt < PRE / 16; bt++) {
            CPWAIT2();
            __syncwarp();
            int base = bt * 16;
            if (base >= limit) break;
            if ((base & 63) == 0) {
                w = base >> 6;
                r = __shfl_sync(0xffffffffu, rem, w);
            }
            ull m[16];
            unsigned keptm = 0;
            if (lane == 0) {
#pragma unroll
                for (int q = 0; q < 16; q++) m[q] = ring[bt & 3][q][w];
                int off = base & 63;
#pragma unroll
                for (int q = 0; q < 16; q++) {
                    int row = base + q;
                    bool keep = (row < limit) && !((r >> (off + q)) & 1ULL);
                    if (keep) {
                        if (kc < POST) sel[kc] = row;
                        kc++;
                        keptm |= 1u << q;
                        r |= m[q];
                    }
                }
            }
            keptm = __shfl_sync(0xffffffffu, keptm, 0);
            ull acc = 0ULL;
#pragma unroll
            for (int q = 0; q < 16; q++)
                if ((keptm >> q) & 1u) acc |= ring[bt & 3][q][lane];
            if (lane >= w) rem |= acc;
            kc = __shfl_sync(0xffffffffu, kc, 0);
            if (kc >= POST) break;
            int nb = bt + 3;
            if (nb < PRE / 16) {
#pragma unroll
                for (int q = 0; q < 16; q++)
                    CP8(smaddr(&ring[nb & 3][q][lane]), &g_mask[b][nb * 16 + q][lane]);
            }
            CPCOMMIT();
        }
        CPWAITALL();
        if (lane == 0) skc = (kc < POST) ? kc : POST;
    }
    __syncthreads();
    int kc = skc;
    for (int k = tid; k < POST; k += blockDim.x) {
        float4 v = make_float4(0.f, 0.f, 0.f, 0.f);
        if (k < kc) v = g_boxes[b][sel[k]];
        out[(size_t)b * POST + k] = v;
    }
    // restore state for next graph replay
    for (int k = tid; k < 2048; k += blockDim.x) g_hist[b][k] = 0u;
    if (tid == 0) g_ccount[b] = 0u;
}

extern "C" void kernel_launch(void* const* d_in, const int* in_sizes, int n_in,
                              void* d_out, int out_size) {
    const float* cls = (const float*)d_in[0];
    const float* reg = (const float*)d_in[1];
    const float* anchors = (const float*)d_in[2];
    float4* out = (float4*)d_out;

    k_hist<<<dim3(NBLK, BB), 256>>>(cls);
    k_compact<<<dim3(NBLK, BB), 256>>>(cls);
    k_sortdecode<<<BB, 1024>>>(reg, anchors);
    k_mask<<<dim3(528, BB), 64>>>();
    k_scan<<<BB, 256>>>(out);
}